// round 5
// baseline (speedup 1.0000x reference)
#include <cuda_runtime.h>
#include <cuda_fp16.h>

#define N_USER 50000
#define N_ITEM 100000
#define NTOT   150000
#define D      64
#define NLAY   3
#define NNZ    2400000
#define BATCH  1024
#define SCANB  1024
#define NBLK   ((NTOT + SCANB - 1) / SCANB)   // 147
#define WST    68                             // padded smem row stride (floats): 16B-aligned rows, conflict-light

// ---------------- scratch (static device globals; no allocation) ----------------
__device__ int      g_rowptr[NTOT + 1];
__device__ int      g_cnt[NTOT];
__device__ int      g_pos[NNZ];
__device__ int      g_bsum[NBLK + 16];
__device__ int      g_boff[NBLK + 16];
__device__ int2     g_ev[NNZ];                           // packed (col, val)
__device__ float    g_E[2][(size_t)NTOT * D];            // ping-pong fp32 (own-row reads)
__device__ unsigned g_Eh[2][(size_t)NTOT * 32];          // ping-pong fp16x2 (gather reads)
__device__ float    g_allE[(size_t)NTOT * 4 * D];        // [E0 | n1 | n2 | n3], row stride 256
__device__ float    g_umlp[BATCH * D];
__device__ int      g_winner[N_USER];

// ---------------- f32x2 helpers ----------------
__device__ __forceinline__ unsigned long long ffma2(unsigned long long a,
                                                    unsigned long long b,
                                                    unsigned long long c) {
    unsigned long long d;
    asm("fma.rn.f32x2 %0, %1, %2, %3;" : "=l"(d) : "l"(a), "l"(b), "l"(c));
    return d;
}
__device__ __forceinline__ float2 unpack2(unsigned long long v) {
    float2 r;
    asm("mov.b64 {%0, %1}, %2;" : "=f"(r.x), "=f"(r.y) : "l"(v));
    return r;
}

// ---------------- CSR build ----------------
__global__ void zero_kernel() {
    int i = blockIdx.x * blockDim.x + threadIdx.x;
    if (i < NTOT) g_cnt[i] = 0;
    if (i < N_USER) g_winner[i] = -1;
}

__global__ void histpos_kernel(const int* __restrict__ lap_row) {
    int e = blockIdx.x * blockDim.x + threadIdx.x;
    if (e < NNZ) g_pos[e] = atomicAdd(&g_cnt[lap_row[e]], 1);
}

__global__ void blockscan_kernel() {
    __shared__ int wsum[32];
    int t = threadIdx.x, lane = t & 31, wid = t >> 5;
    int i = blockIdx.x * SCANB + t;
    int v = (i < NTOT) ? g_cnt[i] : 0;
#pragma unroll
    for (int o = 1; o < 32; o <<= 1) {
        int n = __shfl_up_sync(0xffffffffu, v, o);
        if (lane >= o) v += n;
    }
    if (lane == 31) wsum[wid] = v;
    __syncthreads();
    if (wid == 0) {
        int s = wsum[lane];
#pragma unroll
        for (int o = 1; o < 32; o <<= 1) {
            int n = __shfl_up_sync(0xffffffffu, s, o);
            if (lane >= o) s += n;
        }
        wsum[lane] = s;
    }
    __syncthreads();
    int incl = v + (wid ? wsum[wid - 1] : 0);
    if (i < NTOT) g_cnt[i] = incl;
    if (t == SCANB - 1) g_bsum[blockIdx.x] = incl;
}

__global__ void topscan_kernel() {
    __shared__ int s[256];
    int t = threadIdx.x;
    int v = (t < NBLK) ? g_bsum[t] : 0;
    s[t] = v;
    __syncthreads();
#pragma unroll
    for (int o = 1; o < 256; o <<= 1) {
        int add = (t >= o) ? s[t - o] : 0;
        __syncthreads();
        s[t] += add;
        __syncthreads();
    }
    if (t < NBLK) g_boff[t] = s[t] - v;   // exclusive
}

__global__ void finalize_kernel() {
    int i = blockIdx.x * blockDim.x + threadIdx.x;
    if (i < NTOT) g_rowptr[i + 1] = g_cnt[i] + g_boff[i >> 10];
    if (i == 0) g_rowptr[0] = 0;
}

__global__ void place_kernel(const int* __restrict__ lap_row,
                             const int* __restrict__ lap_col,
                             const float* __restrict__ lap_val) {
    int e = blockIdx.x * blockDim.x + threadIdx.x;
    if (e < NNZ) {
        int r = lap_row[e];
        int p = g_rowptr[r] + g_pos[e];
        g_ev[p] = make_int2(lap_col[e], __float_as_int(lap_val[e]));
    }
}

// ---------------- user MLP + scatter-update ----------------
__global__ void umlp_kernel(const float* __restrict__ feat,
                            const float* __restrict__ w1, const float* __restrict__ b1,
                            const float* __restrict__ w2, const float* __restrict__ b2) {
    __shared__ float h[32];
    __shared__ float f[4];
    int b = blockIdx.x, t = threadIdx.x;
    if (t < 4) f[t] = feat[b * 4 + t];
    __syncthreads();
    if (t < 32) {
        float s = b1[t];
#pragma unroll
        for (int i = 0; i < 4; i++) s = fmaf(f[i], w1[i * 32 + t], s);
        h[t] = s;
    }
    __syncthreads();
    float s = b2[t];
#pragma unroll
    for (int k = 0; k < 32; k++) s = fmaf(h[k], w2[k * 64 + t], s);
    g_umlp[b * 64 + t] = s;
}

__global__ void winner_kernel(const int* __restrict__ user_idx) {
    int i = threadIdx.x;
    atomicMax(&g_winner[user_idx[i]], i);
}

__global__ void initE_kernel(const float* __restrict__ user_emb,
                             const float* __restrict__ item_emb,
                             const float* __restrict__ ratio_p) {
    int gid = blockIdx.x * blockDim.x + threadIdx.x;
    if (gid >= NTOT * 16) return;
    int node = gid >> 4, c = gid & 15;
    float4 v;
    if (node < N_USER) {
        v = reinterpret_cast<const float4*>(user_emb)[node * 16 + c];
        int w = g_winner[node];
        if (w >= 0) {
            float r = *ratio_p;
            float4 m = reinterpret_cast<const float4*>(g_umlp)[w * 16 + c];
            v.x = v.x * (1.0f - r) + m.x * r;
            v.y = v.y * (1.0f - r) + m.y * r;
            v.z = v.z * (1.0f - r) + m.z * r;
            v.w = v.w * (1.0f - r) + m.w * r;
        }
    } else {
        v = reinterpret_cast<const float4*>(item_emb)[(node - N_USER) * 16 + c];
    }
    reinterpret_cast<float4*>(g_E[0])[(size_t)node * 16 + c] = v;
    reinterpret_cast<float4*>(g_allE)[(size_t)node * 64 + c] = v;
    __half2 h01 = __floats2half2_rn(v.x, v.y);
    __half2 h23 = __floats2half2_rn(v.z, v.w);
    uint2 hp;
    hp.x = *reinterpret_cast<unsigned*>(&h01);
    hp.y = *reinterpret_cast<unsigned*>(&h23);
    reinterpret_cast<uint2*>(g_Eh[0])[(size_t)node * 16 + c] = hp;
}

// ---------------- fused layer: SpMM (fp16 gather) + transposed-weight packed-k GEMM ----------------
// dynamic smem layout (floats):
//   w1t [64][WST]   transposed w1: w1t[j][k] = w1[k][j]
//   w2t [64][WST]
//   lie [32][WST]   (L+I)E tile
//   lee [32][WST]   LE .* E tile
#define SM_W1T 0
#define SM_W2T (64 * WST)
#define SM_LIE (2 * 64 * WST)
#define SM_LEE (2 * 64 * WST + 32 * WST)
#define SM_FLOATS (2 * 64 * WST + 2 * 32 * WST)   // 13056 floats = 52224 B

__global__ void __launch_bounds__(256) layer_kernel(int parity,
                                                    const float* __restrict__ w1g,
                                                    const float* __restrict__ b1g,
                                                    const float* __restrict__ w2g,
                                                    const float* __restrict__ b2g,
                                                    int slice, int last) {
    extern __shared__ float sm[];
    float* w1t = sm + SM_W1T;
    float* w2t = sm + SM_W2T;
    float* lie_s = sm + SM_LIE;
    float* lee_s = sm + SM_LEE;

    const float*    __restrict__ Ein   = g_E[parity];
    float*          __restrict__ Eout  = g_E[parity ^ 1];
    const unsigned* __restrict__ Ehin  = g_Eh[parity];
    unsigned*       __restrict__ Ehout = g_Eh[parity ^ 1];

    int tid = threadIdx.x;
    int lane = tid & 31, warp = tid >> 5;
    int rbase = blockIdx.x * 32;

    // stage transposed weights (coalesced gmem reads, 4-way-conflict smem writes; once per block)
    for (int idx = tid; idx < D * D; idx += 256) {
        int k = idx >> 6, j = idx & 63;
        w1t[j * WST + k] = w1g[idx];
        w2t[j * WST + k] = w2g[idx];
    }

    // ---- phase 1: SpMM. warp handles 4 rows; lane owns feature cols {2*lane, 2*lane+1}
    const float2* __restrict__ E2 = reinterpret_cast<const float2*>(Ein);
#pragma unroll
    for (int rr = 0; rr < 4; rr++) {
        int lrow = warp * 4 + rr;
        int row = rbase + lrow;
        float a0 = 0.f, a1 = 0.f;
        float2 er = make_float2(0.f, 0.f);
        if (row < NTOT) {
            int s = g_rowptr[row], e = g_rowptr[row + 1];
            for (int b0 = s; b0 < e; b0 += 32) {
                int idx = b0 + lane;
                int2 ev = make_int2(0, 0);
                if (idx < e) ev = g_ev[idx];
                int m = e - b0; if (m > 32) m = 32;
                for (int j = 0; j < m; j++) {
                    int cc = __shfl_sync(0xffffffffu, ev.x, j);
                    float vv = __int_as_float(__shfl_sync(0xffffffffu, ev.y, j));
                    unsigned hraw = Ehin[(size_t)cc * 32 + lane];
                    float2 evv = __half22float2(*reinterpret_cast<__half2*>(&hraw));
                    a0 = fmaf(vv, evv.x, a0);
                    a1 = fmaf(vv, evv.y, a1);
                }
            }
            er = E2[(size_t)row * 32 + lane];
        }
        float2* dl = reinterpret_cast<float2*>(&lie_s[lrow * WST + 2 * lane]);
        float2* dg = reinterpret_cast<float2*>(&lee_s[lrow * WST + 2 * lane]);
        *dl = make_float2(a0 + er.x, a1 + er.y);   // (L+I)E
        *dg = make_float2(a0 * er.x, a1 * er.y);   // LE .* E
    }
    __syncthreads();

    // ---- phase 2: packed-k dual GEMM. thread -> rows {2*rowg, 2*rowg+1}, cols {4*colg..+3}
    // accumulator = f32x2 (sum over even k, sum over odd k); horizontal add at the end.
    int rowg = tid >> 4, colg = tid & 15;
    int r0 = 2 * rowg, r1 = r0 + 1;
    int c0 = 4 * colg;

    unsigned long long accA[4] = {0ull, 0ull, 0ull, 0ull};
    unsigned long long accB[4] = {0ull, 0ull, 0ull, 0ull};

#pragma unroll 4
    for (int k4 = 0; k4 < D; k4 += 4) {
        ulonglong2 aL0 = *reinterpret_cast<const ulonglong2*>(&lie_s[r0 * WST + k4]);
        ulonglong2 aL1 = *reinterpret_cast<const ulonglong2*>(&lie_s[r1 * WST + k4]);
        ulonglong2 aG0 = *reinterpret_cast<const ulonglong2*>(&lee_s[r0 * WST + k4]);
        ulonglong2 aG1 = *reinterpret_cast<const ulonglong2*>(&lee_s[r1 * WST + k4]);
#pragma unroll
        for (int jj = 0; jj < 4; jj++) {
            ulonglong2 wv1 = *reinterpret_cast<const ulonglong2*>(&w1t[(c0 + jj) * WST + k4]);
            ulonglong2 wv2 = *reinterpret_cast<const ulonglong2*>(&w2t[(c0 + jj) * WST + k4]);
            accA[jj] = ffma2(aL0.x, wv1.x, accA[jj]);
            accA[jj] = ffma2(aL0.y, wv1.y, accA[jj]);
            accA[jj] = ffma2(aG0.x, wv2.x, accA[jj]);
            accA[jj] = ffma2(aG0.y, wv2.y, accA[jj]);
            accB[jj] = ffma2(aL1.x, wv1.x, accB[jj]);
            accB[jj] = ffma2(aL1.y, wv1.y, accB[jj]);
            accB[jj] = ffma2(aG1.x, wv2.x, accB[jj]);
            accB[jj] = ffma2(aG1.y, wv2.y, accB[jj]);
        }
    }

    // ---- epilogue: horizontal add + bias, leaky relu, row norm, stores
    float oA[4], oB[4];
#pragma unroll
    for (int jj = 0; jj < 4; jj++) {
        float b = b1g[c0 + jj] + b2g[c0 + jj];
        float2 tA = unpack2(accA[jj]);
        float2 tB = unpack2(accB[jj]);
        float mA = tA.x + tA.y + b;
        float mB = tB.x + tB.y + b;
        oA[jj] = mA >= 0.f ? mA : 0.2f * mA;
        oB[jj] = mB >= 0.f ? mB : 0.2f * mB;
    }

    float ssA = oA[0] * oA[0] + oA[1] * oA[1] + oA[2] * oA[2] + oA[3] * oA[3];
    float ssB = oB[0] * oB[0] + oB[1] * oB[1] + oB[2] * oB[2] + oB[3] * oB[3];
#pragma unroll
    for (int o = 8; o > 0; o >>= 1) {
        ssA += __shfl_xor_sync(0xffffffffu, ssA, o);
        ssB += __shfl_xor_sync(0xffffffffu, ssB, o);
    }
    float scA = 1.0f / fmaxf(sqrtf(ssA), 1e-12f);
    float scB = 1.0f / fmaxf(sqrtf(ssB), 1e-12f);

    int grow0 = rbase + r0, grow1 = rbase + r1;
    float4* EoutV = reinterpret_cast<float4*>(Eout);
    uint2* EhV = reinterpret_cast<uint2*>(Ehout);
    float4* allEV = reinterpret_cast<float4*>(g_allE);

    if (grow0 < NTOT) {
        if (!last) {
            float4 w = make_float4(oA[0], oA[1], oA[2], oA[3]);
            EoutV[(size_t)grow0 * 16 + colg] = w;
            __half2 h01 = __floats2half2_rn(w.x, w.y);
            __half2 h23 = __floats2half2_rn(w.z, w.w);
            uint2 hp;
            hp.x = *reinterpret_cast<unsigned*>(&h01);
            hp.y = *reinterpret_cast<unsigned*>(&h23);
            EhV[(size_t)grow0 * 16 + colg] = hp;
        }
        allEV[(size_t)grow0 * 64 + slice * 16 + colg] =
            make_float4(oA[0] * scA, oA[1] * scA, oA[2] * scA, oA[3] * scA);
    }
    if (grow1 < NTOT) {
        if (!last) {
            float4 w = make_float4(oB[0], oB[1], oB[2], oB[3]);
            EoutV[(size_t)grow1 * 16 + colg] = w;
            __half2 h01 = __floats2half2_rn(w.x, w.y);
            __half2 h23 = __floats2half2_rn(w.z, w.w);
            uint2 hp;
            hp.x = *reinterpret_cast<unsigned*>(&h01);
            hp.y = *reinterpret_cast<unsigned*>(&h23);
            EhV[(size_t)grow1 * 16 + colg] = hp;
        }
        allEV[(size_t)grow1 * 64 + slice * 16 + colg] =
            make_float4(oB[0] * scB, oB[1] * scB, oB[2] * scB, oB[3] * scB);
    }
}

// ---------------- final gather ----------------
__global__ void out_kernel(const int* __restrict__ uidx,
                           const int* __restrict__ pidx,
                           const int* __restrict__ nidx,
                           float* __restrict__ out) {
    int g = blockIdx.x;
    int b = g & (BATCH - 1);
    int which = g >> 10;
    int row;
    if (which == 0) row = uidx[b];
    else if (which == 1) row = N_USER + pidx[b];
    else row = N_USER + nidx[b];
    const float4* src = reinterpret_cast<const float4*>(g_allE + (size_t)row * 256);
    float4* dst = reinterpret_cast<float4*>(out) + (size_t)g * 64;
    dst[threadIdx.x] = src[threadIdx.x];
}

// ---------------- launch ----------------
extern "C" void kernel_launch(void* const* d_in, const int* in_sizes, int n_in,
                              void* d_out, int out_size) {
    int iUE, iIE, iUF, iL1W, iL1B, iL2W, iL2B, iW1, iB1, iW2, iB2, iLV, iR, iLR, iLC, iUI, iPI, iNI;
    if (n_in >= 18 && in_sizes[2] == 4096) {
        iUE = 0; iIE = 1; iUF = 2; iL1W = 3; iL1B = 4; iL2W = 5; iL2B = 6;
        iW1 = 7; iB1 = 8; iW2 = 9; iB2 = 10; iLV = 11; iR = 12; iLR = 13; iLC = 14;
        iUI = 15; iPI = 16; iNI = 17;
    } else {
        iUE = 0; iIE = 1; iL1W = 2; iL1B = 3; iL2W = 4; iL2B = 5;
        iW1 = 6; iB1 = 7; iW2 = 8; iB2 = 9; iLR = 10; iLC = 11; iLV = 12;
        iUI = 13; iUF = 14; iPI = 15; iNI = 16; iR = 17;
    }

    const float* user_emb = (const float*)d_in[iUE];
    const float* item_emb = (const float*)d_in[iIE];
    const float* user_feat = (const float*)d_in[iUF];
    const float* lin1_w = (const float*)d_in[iL1W];
    const float* lin1_b = (const float*)d_in[iL1B];
    const float* lin2_w = (const float*)d_in[iL2W];
    const float* lin2_b = (const float*)d_in[iL2B];
    const float* w1 = (const float*)d_in[iW1];
    const float* b1 = (const float*)d_in[iB1];
    const float* w2 = (const float*)d_in[iW2];
    const float* b2 = (const float*)d_in[iB2];
    const float* lap_val = (const float*)d_in[iLV];
    const float* ratio = (const float*)d_in[iR];
    const int* lap_row = (const int*)d_in[iLR];
    const int* lap_col = (const int*)d_in[iLC];
    const int* user_idx = (const int*)d_in[iUI];
    const int* pos_idx = (const int*)d_in[iPI];
    const int* neg_idx = (const int*)d_in[iNI];

    static int smem_set = 0;
    if (!smem_set) {
        cudaFuncSetAttribute(layer_kernel, cudaFuncAttributeMaxDynamicSharedMemorySize,
                             SM_FLOATS * (int)sizeof(float));
        smem_set = 1;
    }

    // CSR build: single atomic pass + parallel scan + atomic-free place
    zero_kernel<<<(NTOT + 255) / 256, 256>>>();
    histpos_kernel<<<(NNZ + 255) / 256, 256>>>(lap_row);
    blockscan_kernel<<<NBLK, SCANB>>>();
    topscan_kernel<<<1, 256>>>();
    finalize_kernel<<<(NTOT + 255) / 256, 256>>>();
    place_kernel<<<(NNZ + 255) / 256, 256>>>(lap_row, lap_col, lap_val);

    // user MLP + last-wins scatter update + E0 (fp32 + fp16 copies) + all_E slice 0
    umlp_kernel<<<BATCH, 64>>>(user_feat, lin1_w, lin1_b, lin2_w, lin2_b);
    winner_kernel<<<1, BATCH>>>(user_idx);
    initE_kernel<<<(NTOT * 16 + 255) / 256, 256>>>(user_emb, item_emb, ratio);

    // 3 fused graph-conv layers
    for (int k = 0; k < NLAY; k++) {
        layer_kernel<<<(NTOT + 31) / 32, 256, SM_FLOATS * (int)sizeof(float)>>>(
            k & 1,
            w1 + k * D * D, b1 + k * D,
            w2 + k * D * D, b2 + k * D,
            k + 1, k == NLAY - 1);
    }

    out_kernel<<<3 * BATCH, 64>>>(user_idx, pos_idx, neg_idx, (float*)d_out);
}

// round 6
// speedup vs baseline: 2.3253x; 2.3253x over previous
#include <cuda_runtime.h>
#include <cuda_fp16.h>

#define N_USER 50000
#define N_ITEM 100000
#define NTOT   150000
#define D      64
#define NLAY   3
#define NNZ    2400000
#define BATCH  1024
#define SCANB  1024
#define NBLK   ((NTOT + SCANB - 1) / SCANB)   // 147
#define ASTRIDE 68                            // padded smem row stride (floats)

// ---------------- scratch (static device globals; no allocation) ----------------
__device__ int      g_rowptr[NTOT + 1];
__device__ int      g_cnt[NTOT];
__device__ int      g_pos[NNZ];
__device__ int      g_bsum[NBLK + 16];
__device__ int      g_boff[NBLK + 16];
__device__ int2     g_ev[NNZ];                           // packed (col, val)
__device__ float    g_E[2][(size_t)NTOT * D];            // ping-pong fp32 (own-row reads)
__device__ unsigned g_Eh[2][(size_t)NTOT * 32];          // ping-pong fp16x2 (gather reads)
__device__ float    g_allE[(size_t)NTOT * 4 * D];        // [E0 | n1 | n2 | n3], row stride 256
__device__ float    g_umlp[BATCH * D];
__device__ int      g_winner[N_USER];

// ---------------- f32x2 helpers ----------------
__device__ __forceinline__ unsigned long long pack_dup(float a) {
    unsigned long long r;
    asm("mov.b64 %0, {%1, %1};" : "=l"(r) : "f"(a));
    return r;
}
__device__ __forceinline__ unsigned long long pack2(float x, float y) {
    unsigned long long r;
    asm("mov.b64 %0, {%1, %2};" : "=l"(r) : "f"(x), "f"(y));
    return r;
}
__device__ __forceinline__ float2 unpack2(unsigned long long v) {
    float2 r;
    asm("mov.b64 {%0, %1}, %2;" : "=f"(r.x), "=f"(r.y) : "l"(v));
    return r;
}
__device__ __forceinline__ unsigned long long ffma2(unsigned long long a,
                                                    unsigned long long b,
                                                    unsigned long long c) {
    unsigned long long d;
    asm("fma.rn.f32x2 %0, %1, %2, %3;" : "=l"(d) : "l"(a), "l"(b), "l"(c));
    return d;
}

// ---------------- CSR build ----------------
__global__ void zero_kernel() {
    int i = blockIdx.x * blockDim.x + threadIdx.x;
    if (i < NTOT) g_cnt[i] = 0;
    if (i < N_USER) g_winner[i] = -1;
}

__global__ void histpos_kernel(const int* __restrict__ lap_row) {
    int e = blockIdx.x * blockDim.x + threadIdx.x;
    if (e < NNZ) g_pos[e] = atomicAdd(&g_cnt[lap_row[e]], 1);
}

__global__ void blockscan_kernel() {
    __shared__ int wsum[32];
    int t = threadIdx.x, lane = t & 31, wid = t >> 5;
    int i = blockIdx.x * SCANB + t;
    int v = (i < NTOT) ? g_cnt[i] : 0;
#pragma unroll
    for (int o = 1; o < 32; o <<= 1) {
        int n = __shfl_up_sync(0xffffffffu, v, o);
        if (lane >= o) v += n;
    }
    if (lane == 31) wsum[wid] = v;
    __syncthreads();
    if (wid == 0) {
        int s = wsum[lane];
#pragma unroll
        for (int o = 1; o < 32; o <<= 1) {
            int n = __shfl_up_sync(0xffffffffu, s, o);
            if (lane >= o) s += n;
        }
        wsum[lane] = s;
    }
    __syncthreads();
    int incl = v + (wid ? wsum[wid - 1] : 0);
    if (i < NTOT) g_cnt[i] = incl;
    if (t == SCANB - 1) g_bsum[blockIdx.x] = incl;
}

__global__ void topscan_kernel() {
    __shared__ int s[256];
    int t = threadIdx.x;
    int v = (t < NBLK) ? g_bsum[t] : 0;
    s[t] = v;
    __syncthreads();
#pragma unroll
    for (int o = 1; o < 256; o <<= 1) {
        int add = (t >= o) ? s[t - o] : 0;
        __syncthreads();
        s[t] += add;
        __syncthreads();
    }
    if (t < NBLK) g_boff[t] = s[t] - v;   // exclusive
}

__global__ void finalize_kernel() {
    int i = blockIdx.x * blockDim.x + threadIdx.x;
    if (i < NTOT) g_rowptr[i + 1] = g_cnt[i] + g_boff[i >> 10];
    if (i == 0) g_rowptr[0] = 0;
}

__global__ void place_kernel(const int* __restrict__ lap_row,
                             const int* __restrict__ lap_col,
                             const float* __restrict__ lap_val) {
    int e = blockIdx.x * blockDim.x + threadIdx.x;
    if (e < NNZ) {
        int r = lap_row[e];
        int p = g_rowptr[r] + g_pos[e];
        g_ev[p] = make_int2(lap_col[e], __float_as_int(lap_val[e]));
    }
}

// ---------------- user MLP + scatter-update ----------------
__global__ void umlp_kernel(const float* __restrict__ feat,
                            const float* __restrict__ w1, const float* __restrict__ b1,
                            const float* __restrict__ w2, const float* __restrict__ b2) {
    __shared__ float h[32];
    __shared__ float f[4];
    int b = blockIdx.x, t = threadIdx.x;
    if (t < 4) f[t] = feat[b * 4 + t];
    __syncthreads();
    if (t < 32) {
        float s = b1[t];
#pragma unroll
        for (int i = 0; i < 4; i++) s = fmaf(f[i], w1[i * 32 + t], s);
        h[t] = s;
    }
    __syncthreads();
    float s = b2[t];
#pragma unroll
    for (int k = 0; k < 32; k++) s = fmaf(h[k], w2[k * 64 + t], s);
    g_umlp[b * 64 + t] = s;
}

__global__ void winner_kernel(const int* __restrict__ user_idx) {
    int i = threadIdx.x;
    atomicMax(&g_winner[user_idx[i]], i);
}

__global__ void initE_kernel(const float* __restrict__ user_emb,
                             const float* __restrict__ item_emb,
                             const float* __restrict__ ratio_p) {
    int gid = blockIdx.x * blockDim.x + threadIdx.x;
    if (gid >= NTOT * 16) return;
    int node = gid >> 4, c = gid & 15;
    float4 v;
    if (node < N_USER) {
        v = reinterpret_cast<const float4*>(user_emb)[node * 16 + c];
        int w = g_winner[node];
        if (w >= 0) {
            float r = *ratio_p;
            float4 m = reinterpret_cast<const float4*>(g_umlp)[w * 16 + c];
            v.x = v.x * (1.0f - r) + m.x * r;
            v.y = v.y * (1.0f - r) + m.y * r;
            v.z = v.z * (1.0f - r) + m.z * r;
            v.w = v.w * (1.0f - r) + m.w * r;
        }
    } else {
        v = reinterpret_cast<const float4*>(item_emb)[(node - N_USER) * 16 + c];
    }
    reinterpret_cast<float4*>(g_E[0])[(size_t)node * 16 + c] = v;
    reinterpret_cast<float4*>(g_allE)[(size_t)node * 64 + c] = v;
    __half2 h01 = __floats2half2_rn(v.x, v.y);
    __half2 h23 = __floats2half2_rn(v.z, v.w);
    uint2 hp;
    hp.x = *reinterpret_cast<unsigned*>(&h01);
    hp.y = *reinterpret_cast<unsigned*>(&h23);
    reinterpret_cast<uint2*>(g_Eh[0])[(size_t)node * 16 + c] = hp;
}

// ---------------- fused layer: SpMM (fp16 gather, smem-staged edges, MLP-4) + dual GEMM ----------------
__global__ void __launch_bounds__(256) layer_kernel(int parity,
                                                    const float* __restrict__ w1g,
                                                    const float* __restrict__ b1g,
                                                    const float* __restrict__ w2g,
                                                    const float* __restrict__ b2g,
                                                    int slice, int last) {
    __shared__ __align__(16) float wbuf[D * D];                  // 16 KB, w1 then w2
    __shared__ __align__(16) float lie_s[32 * ASTRIDE];          // 8.7 KB
    __shared__ __align__(16) float lee_s[32 * ASTRIDE];          // 8.7 KB
    __shared__ __align__(16) int2  ebuf[8][32];                  // 2 KB edge staging

    const float*    __restrict__ Ein   = g_E[parity];
    float*          __restrict__ Eout  = g_E[parity ^ 1];
    const unsigned* __restrict__ Ehin  = g_Eh[parity];
    unsigned*       __restrict__ Ehout = g_Eh[parity ^ 1];

    int tid = threadIdx.x;
    int lane = tid & 31, warp = tid >> 5;
    int rbase = blockIdx.x * 32;

    // stage w1 while SpMM runs
    for (int i = tid; i < D * D / 4; i += 256)
        reinterpret_cast<float4*>(wbuf)[i] = reinterpret_cast<const float4*>(w1g)[i];

    // ---- phase 1: SpMM. warp handles 4 rows; lane owns feature cols {2*lane, 2*lane+1}
    const float2* __restrict__ E2 = reinterpret_cast<const float2*>(Ein);
#pragma unroll
    for (int rr = 0; rr < 4; rr++) {
        int lrow = warp * 4 + rr;
        int row = rbase + lrow;
        float a0 = 0.f, a1 = 0.f;
        float2 er = make_float2(0.f, 0.f);
        if (row < NTOT) {
            int s = g_rowptr[row], e = g_rowptr[row + 1];
            for (int b0 = s; b0 < e; b0 += 32) {
                int idx = b0 + lane;
                if (idx < e) ebuf[warp][lane] = g_ev[idx];
                __syncwarp();
                int m = e - b0; if (m > 32) m = 32;
                int j = 0;
                for (; j + 4 <= m; j += 4) {
                    int2 e0 = ebuf[warp][j + 0];
                    int2 e1 = ebuf[warp][j + 1];
                    int2 e2v = ebuf[warp][j + 2];
                    int2 e3 = ebuf[warp][j + 3];
                    unsigned h0 = Ehin[(size_t)e0.x * 32 + lane];
                    unsigned h1 = Ehin[(size_t)e1.x * 32 + lane];
                    unsigned h2 = Ehin[(size_t)e2v.x * 32 + lane];
                    unsigned h3 = Ehin[(size_t)e3.x * 32 + lane];
                    float2 f0 = __half22float2(*reinterpret_cast<__half2*>(&h0));
                    float2 f1 = __half22float2(*reinterpret_cast<__half2*>(&h1));
                    float2 f2 = __half22float2(*reinterpret_cast<__half2*>(&h2));
                    float2 f3 = __half22float2(*reinterpret_cast<__half2*>(&h3));
                    float v0 = __int_as_float(e0.y), v1 = __int_as_float(e1.y);
                    float v2 = __int_as_float(e2v.y), v3 = __int_as_float(e3.y);
                    a0 = fmaf(v0, f0.x, a0); a1 = fmaf(v0, f0.y, a1);
                    a0 = fmaf(v1, f1.x, a0); a1 = fmaf(v1, f1.y, a1);
                    a0 = fmaf(v2, f2.x, a0); a1 = fmaf(v2, f2.y, a1);
                    a0 = fmaf(v3, f3.x, a0); a1 = fmaf(v3, f3.y, a1);
                }
                for (; j < m; j++) {
                    int2 ej = ebuf[warp][j];
                    unsigned hr = Ehin[(size_t)ej.x * 32 + lane];
                    float2 fj = __half22float2(*reinterpret_cast<__half2*>(&hr));
                    float vj = __int_as_float(ej.y);
                    a0 = fmaf(vj, fj.x, a0);
                    a1 = fmaf(vj, fj.y, a1);
                }
                __syncwarp();
            }
            er = E2[(size_t)row * 32 + lane];
        }
        float2* dl = reinterpret_cast<float2*>(&lie_s[lrow * ASTRIDE + 2 * lane]);
        float2* dg = reinterpret_cast<float2*>(&lee_s[lrow * ASTRIDE + 2 * lane]);
        *dl = make_float2(a0 + er.x, a1 + er.y);   // (L+I)E
        *dg = make_float2(a0 * er.x, a1 * er.y);   // LE .* E
    }
    __syncthreads();

    // ---- phase 2: block GEMM (conflict-free wbuf[k][j]). thread -> rows {2*rowg,2*rowg+1}, cols 4*colg..+3
    int rowg = tid >> 4, colg = tid & 15;
    int r0 = 2 * rowg, r1 = r0 + 1;
    int c0 = 4 * colg;

    unsigned long long acc0a, acc0b, acc1a, acc1b;
    {
        float4 bv1 = reinterpret_cast<const float4*>(b1g)[colg];
        float4 bv2 = reinterpret_cast<const float4*>(b2g)[colg];
        acc0a = pack2(bv1.x + bv2.x, bv1.y + bv2.y);
        acc0b = pack2(bv1.z + bv2.z, bv1.w + bv2.w);
        acc1a = acc0a; acc1b = acc0b;
    }

#pragma unroll 4
    for (int k0 = 0; k0 < D; k0 += 4) {
        float4 aA = *reinterpret_cast<const float4*>(&lie_s[r0 * ASTRIDE + k0]);
        float4 aB = *reinterpret_cast<const float4*>(&lie_s[r1 * ASTRIDE + k0]);
#pragma unroll
        for (int kk = 0; kk < 4; kk++) {
            float4 wv = *reinterpret_cast<const float4*>(&wbuf[(k0 + kk) * D + c0]);
            unsigned long long wlo = pack2(wv.x, wv.y);
            unsigned long long whi = pack2(wv.z, wv.w);
            unsigned long long dA = pack_dup((&aA.x)[kk]);
            unsigned long long dB = pack_dup((&aB.x)[kk]);
            acc0a = ffma2(dA, wlo, acc0a);
            acc0b = ffma2(dA, whi, acc0b);
            acc1a = ffma2(dB, wlo, acc1a);
            acc1b = ffma2(dB, whi, acc1b);
        }
    }
    __syncthreads();

    // reload weight buffer with w2
    for (int i = tid; i < D * D / 4; i += 256)
        reinterpret_cast<float4*>(wbuf)[i] = reinterpret_cast<const float4*>(w2g)[i];
    __syncthreads();

#pragma unroll 4
    for (int k0 = 0; k0 < D; k0 += 4) {
        float4 aA = *reinterpret_cast<const float4*>(&lee_s[r0 * ASTRIDE + k0]);
        float4 aB = *reinterpret_cast<const float4*>(&lee_s[r1 * ASTRIDE + k0]);
#pragma unroll
        for (int kk = 0; kk < 4; kk++) {
            float4 wv = *reinterpret_cast<const float4*>(&wbuf[(k0 + kk) * D + c0]);
            unsigned long long wlo = pack2(wv.x, wv.y);
            unsigned long long whi = pack2(wv.z, wv.w);
            unsigned long long dA = pack_dup((&aA.x)[kk]);
            unsigned long long dB = pack_dup((&aB.x)[kk]);
            acc0a = ffma2(dA, wlo, acc0a);
            acc0b = ffma2(dA, whi, acc0b);
            acc1a = ffma2(dB, wlo, acc1a);
            acc1b = ffma2(dB, whi, acc1b);
        }
    }

    // ---- epilogue: leaky relu, row norm (16 threads share a row), stores
    float2 o0a = unpack2(acc0a), o0b = unpack2(acc0b);
    float2 o1a = unpack2(acc1a), o1b = unpack2(acc1b);
    o0a.x = o0a.x >= 0.f ? o0a.x : 0.2f * o0a.x;
    o0a.y = o0a.y >= 0.f ? o0a.y : 0.2f * o0a.y;
    o0b.x = o0b.x >= 0.f ? o0b.x : 0.2f * o0b.x;
    o0b.y = o0b.y >= 0.f ? o0b.y : 0.2f * o0b.y;
    o1a.x = o1a.x >= 0.f ? o1a.x : 0.2f * o1a.x;
    o1a.y = o1a.y >= 0.f ? o1a.y : 0.2f * o1a.y;
    o1b.x = o1b.x >= 0.f ? o1b.x : 0.2f * o1b.x;
    o1b.y = o1b.y >= 0.f ? o1b.y : 0.2f * o1b.y;

    float ss0 = o0a.x * o0a.x + o0a.y * o0a.y + o0b.x * o0b.x + o0b.y * o0b.y;
    float ss1 = o1a.x * o1a.x + o1a.y * o1a.y + o1b.x * o1b.x + o1b.y * o1b.y;
#pragma unroll
    for (int o = 8; o > 0; o >>= 1) {
        ss0 += __shfl_xor_sync(0xffffffffu, ss0, o);
        ss1 += __shfl_xor_sync(0xffffffffu, ss1, o);
    }
    float sc0 = 1.0f / fmaxf(sqrtf(ss0), 1e-12f);
    float sc1 = 1.0f / fmaxf(sqrtf(ss1), 1e-12f);

    int grow0 = rbase + r0, grow1 = rbase + r1;
    float4* EoutV = reinterpret_cast<float4*>(Eout);
    uint2* EhV = reinterpret_cast<uint2*>(Ehout);
    float4* allEV = reinterpret_cast<float4*>(g_allE);

    if (grow0 < NTOT) {
        if (!last) {
            float4 w = make_float4(o0a.x, o0a.y, o0b.x, o0b.y);
            EoutV[(size_t)grow0 * 16 + colg] = w;
            __half2 h01 = __floats2half2_rn(w.x, w.y);
            __half2 h23 = __floats2half2_rn(w.z, w.w);
            uint2 hp;
            hp.x = *reinterpret_cast<unsigned*>(&h01);
            hp.y = *reinterpret_cast<unsigned*>(&h23);
            EhV[(size_t)grow0 * 16 + colg] = hp;
        }
        allEV[(size_t)grow0 * 64 + slice * 16 + colg] =
            make_float4(o0a.x * sc0, o0a.y * sc0, o0b.x * sc0, o0b.y * sc0);
    }
    if (grow1 < NTOT) {
        if (!last) {
            float4 w = make_float4(o1a.x, o1a.y, o1b.x, o1b.y);
            EoutV[(size_t)grow1 * 16 + colg] = w;
            __half2 h01 = __floats2half2_rn(w.x, w.y);
            __half2 h23 = __floats2half2_rn(w.z, w.w);
            uint2 hp;
            hp.x = *reinterpret_cast<unsigned*>(&h01);
            hp.y = *reinterpret_cast<unsigned*>(&h23);
            EhV[(size_t)grow1 * 16 + colg] = hp;
        }
        allEV[(size_t)grow1 * 64 + slice * 16 + colg] =
            make_float4(o1a.x * sc1, o1a.y * sc1, o1b.x * sc1, o1b.y * sc1);
    }
}

// ---------------- final gather ----------------
__global__ void out_kernel(const int* __restrict__ uidx,
                           const int* __restrict__ pidx,
                           const int* __restrict__ nidx,
                           float* __restrict__ out) {
    int g = blockIdx.x;
    int b = g & (BATCH - 1);
    int which = g >> 10;
    int row;
    if (which == 0) row = uidx[b];
    else if (which == 1) row = N_USER + pidx[b];
    else row = N_USER + nidx[b];
    const float4* src = reinterpret_cast<const float4*>(g_allE + (size_t)row * 256);
    float4* dst = reinterpret_cast<float4*>(out) + (size_t)g * 64;
    dst[threadIdx.x] = src[threadIdx.x];
}

// ---------------- launch ----------------
extern "C" void kernel_launch(void* const* d_in, const int* in_sizes, int n_in,
                              void* d_out, int out_size) {
    int iUE, iIE, iUF, iL1W, iL1B, iL2W, iL2B, iW1, iB1, iW2, iB2, iLV, iR, iLR, iLC, iUI, iPI, iNI;
    if (n_in >= 18 && in_sizes[2] == 4096) {
        iUE = 0; iIE = 1; iUF = 2; iL1W = 3; iL1B = 4; iL2W = 5; iL2B = 6;
        iW1 = 7; iB1 = 8; iW2 = 9; iB2 = 10; iLV = 11; iR = 12; iLR = 13; iLC = 14;
        iUI = 15; iPI = 16; iNI = 17;
    } else {
        iUE = 0; iIE = 1; iL1W = 2; iL1B = 3; iL2W = 4; iL2B = 5;
        iW1 = 6; iB1 = 7; iW2 = 8; iB2 = 9; iLR = 10; iLC = 11; iLV = 12;
        iUI = 13; iUF = 14; iPI = 15; iNI = 16; iR = 17;
    }

    const float* user_emb = (const float*)d_in[iUE];
    const float* item_emb = (const float*)d_in[iIE];
    const float* user_feat = (const float*)d_in[iUF];
    const float* lin1_w = (const float*)d_in[iL1W];
    const float* lin1_b = (const float*)d_in[iL1B];
    const float* lin2_w = (const float*)d_in[iL2W];
    const float* lin2_b = (const float*)d_in[iL2B];
    const float* w1 = (const float*)d_in[iW1];
    const float* b1 = (const float*)d_in[iB1];
    const float* w2 = (const float*)d_in[iW2];
    const float* b2 = (const float*)d_in[iB2];
    const float* lap_val = (const float*)d_in[iLV];
    const float* ratio = (const float*)d_in[iR];
    const int* lap_row = (const int*)d_in[iLR];
    const int* lap_col = (const int*)d_in[iLC];
    const int* user_idx = (const int*)d_in[iUI];
    const int* pos_idx = (const int*)d_in[iPI];
    const int* neg_idx = (const int*)d_in[iNI];

    // CSR build: single atomic pass + parallel scan + atomic-free place
    zero_kernel<<<(NTOT + 255) / 256, 256>>>();
    histpos_kernel<<<(NNZ + 255) / 256, 256>>>(lap_row);
    blockscan_kernel<<<NBLK, SCANB>>>();
    topscan_kernel<<<1, 256>>>();
    finalize_kernel<<<(NTOT + 255) / 256, 256>>>();
    place_kernel<<<(NNZ + 255) / 256, 256>>>(lap_row, lap_col, lap_val);

    // user MLP + last-wins scatter update + E0 (fp32 + fp16 copies) + all_E slice 0
    umlp_kernel<<<BATCH, 64>>>(user_feat, lin1_w, lin1_b, lin2_w, lin2_b);
    winner_kernel<<<1, BATCH>>>(user_idx);
    initE_kernel<<<(NTOT * 16 + 255) / 256, 256>>>(user_emb, item_emb, ratio);

    // 3 fused graph-conv layers
    for (int k = 0; k < NLAY; k++) {
        layer_kernel<<<(NTOT + 31) / 32, 256>>>(k & 1,
                                                w1 + k * D * D, b1 + k * D,
                                                w2 + k * D * D, b2 + k * D,
                                                k + 1, k == NLAY - 1);
    }

    out_kernel<<<3 * BATCH, 64>>>(user_idx, pos_idx, neg_idx, (float*)d_out);
}

// round 7
// speedup vs baseline: 2.5381x; 1.0915x over previous
#include <cuda_runtime.h>
#include <cuda_fp16.h>

#define N_USER 50000
#define N_ITEM 100000
#define NTOT   150000
#define D      64
#define NLAY   3
#define NNZ    2400000
#define BATCH  1024
#define SCANB  1024
#define NBLK   ((NTOT + SCANB - 1) / SCANB)   // 147
#define ASTRIDE 68                            // padded smem row stride (floats)

// ---------------- scratch (static device globals; no allocation) ----------------
__device__ int      g_rowptr[NTOT + 1];
__device__ int      g_cnt[NTOT];              // zero at load; re-zeroed each call
__device__ int      g_pos[NNZ];
__device__ int      g_bsum[NBLK + 16];
__device__ int      g_boff[NBLK + 16];
__device__ int2     g_ev[NNZ];                           // packed (col, val)
__device__ float    g_Ebuf[4][(size_t)NTOT * D];         // E0, L1, L2, L3 (unnormalized, post-act)
__device__ unsigned g_Eh[2][(size_t)NTOT * 32];          // fp16x2 ping-pong (gather reads)
__device__ float    g_umlp[BATCH * D];
__device__ int      g_winner[N_USER];         // 0 = none, else batch_idx+1; zero at load; reset each call

// ---------------- f32x2 helpers ----------------
__device__ __forceinline__ unsigned long long pack_dup(float a) {
    unsigned long long r;
    asm("mov.b64 %0, {%1, %1};" : "=l"(r) : "f"(a));
    return r;
}
__device__ __forceinline__ unsigned long long pack2(float x, float y) {
    unsigned long long r;
    asm("mov.b64 %0, {%1, %2};" : "=l"(r) : "f"(x), "f"(y));
    return r;
}
__device__ __forceinline__ float2 unpack2(unsigned long long v) {
    float2 r;
    asm("mov.b64 {%0, %1}, %2;" : "=f"(r.x), "=f"(r.y) : "l"(v));
    return r;
}
__device__ __forceinline__ unsigned long long ffma2(unsigned long long a,
                                                    unsigned long long b,
                                                    unsigned long long c) {
    unsigned long long d;
    asm("fma.rn.f32x2 %0, %1, %2, %3;" : "=l"(d) : "l"(a), "l"(b), "l"(c));
    return d;
}

// ---------------- kernel 1: umlp + winner + histpos (fused) ----------------
__global__ void fused1_kernel(const float* __restrict__ feat,
                              const float* __restrict__ l1w, const float* __restrict__ l1b,
                              const float* __restrict__ l2w, const float* __restrict__ l2b,
                              const int* __restrict__ user_idx,
                              const int* __restrict__ lap_row) {
    __shared__ float h[32];
    __shared__ float f[4];
    int b = blockIdx.x, t = threadIdx.x;
    if (b < BATCH) {
        if (t < 4) f[t] = feat[b * 4 + t];
        __syncthreads();
        if (t < 32) {
            float s = l1b[t];
#pragma unroll
            for (int i = 0; i < 4; i++) s = fmaf(f[i], l1w[i * 32 + t], s);
            h[t] = s;
        }
        __syncthreads();
        if (t < 64) {
            float s = l2b[t];
#pragma unroll
            for (int k = 0; k < 32; k++) s = fmaf(h[k], l2w[k * 64 + t], s);
            g_umlp[b * 64 + t] = s;
        }
        if (t == 0) atomicMax(&g_winner[user_idx[b]], b + 1);
    }
    int e = b * 256 + t;
    if (e < NNZ) g_pos[e] = atomicAdd(&g_cnt[lap_row[e]], 1);
}

// ---------------- kernel 2/3: scan ----------------
__global__ void blockscan_kernel() {
    __shared__ int wsum[32];
    int t = threadIdx.x, lane = t & 31, wid = t >> 5;
    int i = blockIdx.x * SCANB + t;
    int v = (i < NTOT) ? g_cnt[i] : 0;
#pragma unroll
    for (int o = 1; o < 32; o <<= 1) {
        int n = __shfl_up_sync(0xffffffffu, v, o);
        if (lane >= o) v += n;
    }
    if (lane == 31) wsum[wid] = v;
    __syncthreads();
    if (wid == 0) {
        int s = wsum[lane];
#pragma unroll
        for (int o = 1; o < 32; o <<= 1) {
            int n = __shfl_up_sync(0xffffffffu, s, o);
            if (lane >= o) s += n;
        }
        wsum[lane] = s;
    }
    __syncthreads();
    int incl = v + (wid ? wsum[wid - 1] : 0);
    if (i < NTOT) g_cnt[i] = incl;
    if (t == SCANB - 1) g_bsum[blockIdx.x] = incl;
}

__global__ void topscan_kernel() {
    __shared__ int s[256];
    int t = threadIdx.x;
    int v = (t < NBLK) ? g_bsum[t] : 0;
    s[t] = v;
    __syncthreads();
#pragma unroll
    for (int o = 1; o < 256; o <<= 1) {
        int add = (t >= o) ? s[t - o] : 0;
        __syncthreads();
        s[t] += add;
        __syncthreads();
    }
    if (t < NBLK) g_boff[t] = s[t] - v;   // exclusive
}

// ---------------- kernel 4: initE + finalize rowptr + reset g_cnt ----------------
__global__ void initE_kernel(const float* __restrict__ user_emb,
                             const float* __restrict__ item_emb,
                             const float* __restrict__ ratio_p) {
    int gid = blockIdx.x * blockDim.x + threadIdx.x;
    // finalize rowptr + g_cnt reset
    if (gid < NTOT) {
        g_rowptr[gid + 1] = g_cnt[gid] + g_boff[gid >> 10];
        g_cnt[gid] = 0;
        if (gid == 0) g_rowptr[0] = 0;
    }
    if (gid >= NTOT * 16) return;
    int node = gid >> 4, c = gid & 15;
    float4 v;
    if (node < N_USER) {
        v = reinterpret_cast<const float4*>(user_emb)[node * 16 + c];
        int w = g_winner[node] - 1;
        if (w >= 0) {
            float r = *ratio_p;
            float4 m = reinterpret_cast<const float4*>(g_umlp)[w * 16 + c];
            v.x = v.x * (1.0f - r) + m.x * r;
            v.y = v.y * (1.0f - r) + m.y * r;
            v.z = v.z * (1.0f - r) + m.z * r;
            v.w = v.w * (1.0f - r) + m.w * r;
        }
    } else {
        v = reinterpret_cast<const float4*>(item_emb)[(node - N_USER) * 16 + c];
    }
    reinterpret_cast<float4*>(g_Ebuf[0])[(size_t)node * 16 + c] = v;
    __half2 h01 = __floats2half2_rn(v.x, v.y);
    __half2 h23 = __floats2half2_rn(v.z, v.w);
    uint2 hp;
    hp.x = *reinterpret_cast<unsigned*>(&h01);
    hp.y = *reinterpret_cast<unsigned*>(&h23);
    reinterpret_cast<uint2*>(g_Eh[0])[(size_t)node * 16 + c] = hp;
}

// ---------------- kernel 5: place edges + reset g_winner ----------------
__global__ void place_kernel(const int* __restrict__ lap_row,
                             const int* __restrict__ lap_col,
                             const float* __restrict__ lap_val) {
    int e = blockIdx.x * blockDim.x + threadIdx.x;
    if (e < NNZ) {
        int r = lap_row[e];
        int p = g_rowptr[r] + g_pos[e];
        g_ev[p] = make_int2(lap_col[e], __float_as_int(lap_val[e]));
    }
    if (e < N_USER) g_winner[e] = 0;
}

// ---------------- layer: SpMM (fp16 gather, smem-staged edges) + dual GEMM + leaky ----------------
__global__ void __launch_bounds__(256) layer_kernel(int kin,
                                                    const float* __restrict__ w1g,
                                                    const float* __restrict__ b1g,
                                                    const float* __restrict__ w2g,
                                                    const float* __restrict__ b2g,
                                                    int last) {
    __shared__ __align__(16) float wbuf[D * D];                  // 16 KB, w1 then w2
    __shared__ __align__(16) float lie_s[32 * ASTRIDE];          // 8.7 KB
    __shared__ __align__(16) float lee_s[32 * ASTRIDE];          // 8.7 KB
    __shared__ __align__(16) int2  ebuf[8][32];                  // 2 KB edge staging

    const float*    __restrict__ Ein   = g_Ebuf[kin];
    float*          __restrict__ Eout  = g_Ebuf[kin + 1];
    const unsigned* __restrict__ Ehin  = g_Eh[kin & 1];
    unsigned*       __restrict__ Ehout = g_Eh[(kin + 1) & 1];

    int tid = threadIdx.x;
    int lane = tid & 31, warp = tid >> 5;
    int rbase = blockIdx.x * 32;

    // stage w1 while SpMM runs
    for (int i = tid; i < D * D / 4; i += 256)
        reinterpret_cast<float4*>(wbuf)[i] = reinterpret_cast<const float4*>(w1g)[i];

    // ---- phase 1: SpMM. warp handles 4 rows; lane owns feature cols {2*lane, 2*lane+1}
    const float2* __restrict__ E2 = reinterpret_cast<const float2*>(Ein);
#pragma unroll
    for (int rr = 0; rr < 4; rr++) {
        int lrow = warp * 4 + rr;
        int row = rbase + lrow;
        float a0 = 0.f, a1 = 0.f;
        float2 er = make_float2(0.f, 0.f);
        if (row < NTOT) {
            er = E2[(size_t)row * 32 + lane];   // own row: independent load up front
            int s = g_rowptr[row], e = g_rowptr[row + 1];
            for (int b0 = s; b0 < e; b0 += 32) {
                int idx = b0 + lane;
                if (idx < e) ebuf[warp][lane] = g_ev[idx];
                __syncwarp();
                int m = e - b0; if (m > 32) m = 32;
                int j = 0;
                for (; j + 4 <= m; j += 4) {
                    int2 e0 = ebuf[warp][j + 0];
                    int2 e1 = ebuf[warp][j + 1];
                    int2 e2v = ebuf[warp][j + 2];
                    int2 e3 = ebuf[warp][j + 3];
                    unsigned h0 = Ehin[(size_t)e0.x * 32 + lane];
                    unsigned h1 = Ehin[(size_t)e1.x * 32 + lane];
                    unsigned h2 = Ehin[(size_t)e2v.x * 32 + lane];
                    unsigned h3 = Ehin[(size_t)e3.x * 32 + lane];
                    float2 f0 = __half22float2(*reinterpret_cast<__half2*>(&h0));
                    float2 f1 = __half22float2(*reinterpret_cast<__half2*>(&h1));
                    float2 f2 = __half22float2(*reinterpret_cast<__half2*>(&h2));
                    float2 f3 = __half22float2(*reinterpret_cast<__half2*>(&h3));
                    float v0 = __int_as_float(e0.y), v1 = __int_as_float(e1.y);
                    float v2 = __int_as_float(e2v.y), v3 = __int_as_float(e3.y);
                    a0 = fmaf(v0, f0.x, a0); a1 = fmaf(v0, f0.y, a1);
                    a0 = fmaf(v1, f1.x, a0); a1 = fmaf(v1, f1.y, a1);
                    a0 = fmaf(v2, f2.x, a0); a1 = fmaf(v2, f2.y, a1);
                    a0 = fmaf(v3, f3.x, a0); a1 = fmaf(v3, f3.y, a1);
                }
                for (; j < m; j++) {
                    int2 ej = ebuf[warp][j];
                    unsigned hr = Ehin[(size_t)ej.x * 32 + lane];
                    float2 fj = __half22float2(*reinterpret_cast<__half2*>(&hr));
                    float vj = __int_as_float(ej.y);
                    a0 = fmaf(vj, fj.x, a0);
                    a1 = fmaf(vj, fj.y, a1);
                }
                __syncwarp();
            }
        }
        float2* dl = reinterpret_cast<float2*>(&lie_s[lrow * ASTRIDE + 2 * lane]);
        float2* dg = reinterpret_cast<float2*>(&lee_s[lrow * ASTRIDE + 2 * lane]);
        *dl = make_float2(a0 + er.x, a1 + er.y);   // (L+I)E
        *dg = make_float2(a0 * er.x, a1 * er.y);   // LE .* E
    }
    __syncthreads();

    // ---- phase 2: block GEMM (conflict-free wbuf[k][j]). thread -> rows {2*rowg,2*rowg+1}, cols 4*colg..+3
    int rowg = tid >> 4, colg = tid & 15;
    int r0 = 2 * rowg, r1 = r0 + 1;
    int c0 = 4 * colg;

    unsigned long long acc0a, acc0b, acc1a, acc1b;
    {
        float4 bv1 = reinterpret_cast<const float4*>(b1g)[colg];
        float4 bv2 = reinterpret_cast<const float4*>(b2g)[colg];
        acc0a = pack2(bv1.x + bv2.x, bv1.y + bv2.y);
        acc0b = pack2(bv1.z + bv2.z, bv1.w + bv2.w);
        acc1a = acc0a; acc1b = acc0b;
    }

#pragma unroll 4
    for (int k0 = 0; k0 < D; k0 += 4) {
        float4 aA = *reinterpret_cast<const float4*>(&lie_s[r0 * ASTRIDE + k0]);
        float4 aB = *reinterpret_cast<const float4*>(&lie_s[r1 * ASTRIDE + k0]);
#pragma unroll
        for (int kk = 0; kk < 4; kk++) {
            float4 wv = *reinterpret_cast<const float4*>(&wbuf[(k0 + kk) * D + c0]);
            unsigned long long wlo = pack2(wv.x, wv.y);
            unsigned long long whi = pack2(wv.z, wv.w);
            unsigned long long dA = pack_dup((&aA.x)[kk]);
            unsigned long long dB = pack_dup((&aB.x)[kk]);
            acc0a = ffma2(dA, wlo, acc0a);
            acc0b = ffma2(dA, whi, acc0b);
            acc1a = ffma2(dB, wlo, acc1a);
            acc1b = ffma2(dB, whi, acc1b);
        }
    }
    __syncthreads();

    // reload weight buffer with w2
    for (int i = tid; i < D * D / 4; i += 256)
        reinterpret_cast<float4*>(wbuf)[i] = reinterpret_cast<const float4*>(w2g)[i];
    __syncthreads();

#pragma unroll 4
    for (int k0 = 0; k0 < D; k0 += 4) {
        float4 aA = *reinterpret_cast<const float4*>(&lee_s[r0 * ASTRIDE + k0]);
        float4 aB = *reinterpret_cast<const float4*>(&lee_s[r1 * ASTRIDE + k0]);
#pragma unroll
        for (int kk = 0; kk < 4; kk++) {
            float4 wv = *reinterpret_cast<const float4*>(&wbuf[(k0 + kk) * D + c0]);
            unsigned long long wlo = pack2(wv.x, wv.y);
            unsigned long long whi = pack2(wv.z, wv.w);
            unsigned long long dA = pack_dup((&aA.x)[kk]);
            unsigned long long dB = pack_dup((&aB.x)[kk]);
            acc0a = ffma2(dA, wlo, acc0a);
            acc0b = ffma2(dA, whi, acc0b);
            acc1a = ffma2(dB, wlo, acc1a);
            acc1b = ffma2(dB, whi, acc1b);
        }
    }

    // ---- epilogue: leaky relu + stores (no norm — deferred to out_kernel)
    float2 o0a = unpack2(acc0a), o0b = unpack2(acc0b);
    float2 o1a = unpack2(acc1a), o1b = unpack2(acc1b);
    o0a.x = o0a.x >= 0.f ? o0a.x : 0.2f * o0a.x;
    o0a.y = o0a.y >= 0.f ? o0a.y : 0.2f * o0a.y;
    o0b.x = o0b.x >= 0.f ? o0b.x : 0.2f * o0b.x;
    o0b.y = o0b.y >= 0.f ? o0b.y : 0.2f * o0b.y;
    o1a.x = o1a.x >= 0.f ? o1a.x : 0.2f * o1a.x;
    o1a.y = o1a.y >= 0.f ? o1a.y : 0.2f * o1a.y;
    o1b.x = o1b.x >= 0.f ? o1b.x : 0.2f * o1b.x;
    o1b.y = o1b.y >= 0.f ? o1b.y : 0.2f * o1b.y;

    int grow0 = rbase + r0, grow1 = rbase + r1;
    float4* EoutV = reinterpret_cast<float4*>(Eout);
    uint2* EhV = reinterpret_cast<uint2*>(Ehout);

    if (grow0 < NTOT) {
        float4 w = make_float4(o0a.x, o0a.y, o0b.x, o0b.y);
        EoutV[(size_t)grow0 * 16 + colg] = w;
        if (!last) {
            __half2 h01 = __floats2half2_rn(w.x, w.y);
            __half2 h23 = __floats2half2_rn(w.z, w.w);
            uint2 hp;
            hp.x = *reinterpret_cast<unsigned*>(&h01);
            hp.y = *reinterpret_cast<unsigned*>(&h23);
            EhV[(size_t)grow0 * 16 + colg] = hp;
        }
    }
    if (grow1 < NTOT) {
        float4 w = make_float4(o1a.x, o1a.y, o1b.x, o1b.y);
        EoutV[(size_t)grow1 * 16 + colg] = w;
        if (!last) {
            __half2 h01 = __floats2half2_rn(w.x, w.y);
            __half2 h23 = __floats2half2_rn(w.z, w.w);
            uint2 hp;
            hp.x = *reinterpret_cast<unsigned*>(&h01);
            hp.y = *reinterpret_cast<unsigned*>(&h23);
            EhV[(size_t)grow1 * 16 + colg] = hp;
        }
    }
}

// ---------------- final gather + deferred normalization ----------------
__global__ void out_kernel(const int* __restrict__ uidx,
                           const int* __restrict__ pidx,
                           const int* __restrict__ nidx,
                           float* __restrict__ out) {
    int warp = threadIdx.x >> 5, lane = threadIdx.x & 31;
    int g = blockIdx.x * 8 + warp;            // 0..3071
    int b = g & (BATCH - 1);
    int which = g >> 10;
    int row;
    if (which == 0) row = uidx[b];
    else if (which == 1) row = N_USER + pidx[b];
    else row = N_USER + nidx[b];

    float2* dst = reinterpret_cast<float2*>(out) + (size_t)g * 128;
#pragma unroll
    for (int k = 0; k < 4; k++) {
        float2 v = reinterpret_cast<const float2*>(g_Ebuf[k])[(size_t)row * 32 + lane];
        float sc = 1.0f;
        if (k > 0) {
            float ss = v.x * v.x + v.y * v.y;
#pragma unroll
            for (int o = 16; o > 0; o >>= 1) ss += __shfl_xor_sync(0xffffffffu, ss, o);
            sc = 1.0f / fmaxf(sqrtf(ss), 1e-12f);
        }
        dst[k * 32 + lane] = make_float2(v.x * sc, v.y * sc);
    }
}

// ---------------- launch ----------------
extern "C" void kernel_launch(void* const* d_in, const int* in_sizes, int n_in,
                              void* d_out, int out_size) {
    int iUE, iIE, iUF, iL1W, iL1B, iL2W, iL2B, iW1, iB1, iW2, iB2, iLV, iR, iLR, iLC, iUI, iPI, iNI;
    if (n_in >= 18 && in_sizes[2] == 4096) {
        iUE = 0; iIE = 1; iUF = 2; iL1W = 3; iL1B = 4; iL2W = 5; iL2B = 6;
        iW1 = 7; iB1 = 8; iW2 = 9; iB2 = 10; iLV = 11; iR = 12; iLR = 13; iLC = 14;
        iUI = 15; iPI = 16; iNI = 17;
    } else {
        iUE = 0; iIE = 1; iL1W = 2; iL1B = 3; iL2W = 4; iL2B = 5;
        iW1 = 6; iB1 = 7; iW2 = 8; iB2 = 9; iLR = 10; iLC = 11; iLV = 12;
        iUI = 13; iUF = 14; iPI = 15; iNI = 16; iR = 17;
    }

    const float* user_emb = (const float*)d_in[iUE];
    const float* item_emb = (const float*)d_in[iIE];
    const float* user_feat = (const float*)d_in[iUF];
    const float* lin1_w = (const float*)d_in[iL1W];
    const float* lin1_b = (const float*)d_in[iL1B];
    const float* lin2_w = (const float*)d_in[iL2W];
    const float* lin2_b = (const float*)d_in[iL2B];
    const float* w1 = (const float*)d_in[iW1];
    const float* b1 = (const float*)d_in[iB1];
    const float* w2 = (const float*)d_in[iW2];
    const float* b2 = (const float*)d_in[iB2];
    const float* lap_val = (const float*)d_in[iLV];
    const float* ratio = (const float*)d_in[iR];
    const int* lap_row = (const int*)d_in[iLR];
    const int* lap_col = (const int*)d_in[iLC];
    const int* user_idx = (const int*)d_in[iUI];
    const int* pos_idx = (const int*)d_in[iPI];
    const int* neg_idx = (const int*)d_in[iNI];

    // 1: user MLP + winner + edge histogram/position (one pass)
    fused1_kernel<<<(NNZ + 255) / 256, 256>>>(user_feat, lin1_w, lin1_b, lin2_w, lin2_b,
                                              user_idx, lap_row);
    // 2-3: scan
    blockscan_kernel<<<NBLK, SCANB>>>();
    topscan_kernel<<<1, 256>>>();
    // 4: E0 init (+ finalize rowptr, reset g_cnt)
    initE_kernel<<<(NTOT * 16 + 255) / 256, 256>>>(user_emb, item_emb, ratio);
    // 5: place edges (+ reset g_winner)
    place_kernel<<<(NNZ + 255) / 256, 256>>>(lap_row, lap_col, lap_val);

    // 6-8: 3 fused graph-conv layers
    for (int k = 0; k < NLAY; k++) {
        layer_kernel<<<(NTOT + 31) / 32, 256>>>(k,
                                                w1 + k * D * D, b1 + k * D,
                                                w2 + k * D * D, b2 + k * D,
                                                k == NLAY - 1);
    }

    // 9: gather + deferred normalization
    out_kernel<<<3 * BATCH / 8, 256>>>(user_idx, pos_idx, neg_idx, (float*)d_out);
}

// round 8
// speedup vs baseline: 2.5887x; 1.0199x over previous
#include <cuda_runtime.h>
#include <cuda_fp16.h>

#define N_USER 50000
#define N_ITEM 100000
#define NTOT   150000
#define D      64
#define NLAY   3
#define NNZ    2400000
#define BATCH  1024
#define SCANB  1024
#define NBLK   ((NTOT + SCANB - 1) / SCANB)   // 147
#define ASTRIDE 68                            // padded smem row stride (floats)

// ---------------- scratch (static device globals; no allocation) ----------------
__device__ int      g_rowptr[NTOT + 1];
__device__ int      g_cnt[NTOT];              // zero at load; re-zeroed each call
__device__ int      g_pos[NNZ];
__device__ int      g_bsum[NBLK + 16];
__device__ int      g_boff[NBLK + 16];
__device__ int2     g_ev[NNZ];                // packed (col, half2(val,val))
__device__ float    g_Ebuf[4][(size_t)NTOT * D];         // E0, L1, L2, L3 (unnormalized, post-act)
__device__ unsigned g_Eh[2][(size_t)NTOT * 32];          // fp16x2 ping-pong (gather reads)
__device__ float    g_umlp[BATCH * D];
__device__ int      g_winner[N_USER];         // 0 = none, else batch_idx+1; reset each call

// ---------------- f32x2 helpers ----------------
__device__ __forceinline__ unsigned long long pack_dup(float a) {
    unsigned long long r;
    asm("mov.b64 %0, {%1, %1};" : "=l"(r) : "f"(a));
    return r;
}
__device__ __forceinline__ unsigned long long pack2(float x, float y) {
    unsigned long long r;
    asm("mov.b64 %0, {%1, %2};" : "=l"(r) : "f"(x), "f"(y));
    return r;
}
__device__ __forceinline__ float2 unpack2(unsigned long long v) {
    float2 r;
    asm("mov.b64 {%0, %1}, %2;" : "=f"(r.x), "=f"(r.y) : "l"(v));
    return r;
}
__device__ __forceinline__ unsigned long long ffma2(unsigned long long a,
                                                    unsigned long long b,
                                                    unsigned long long c) {
    unsigned long long d;
    asm("fma.rn.f32x2 %0, %1, %2, %3;" : "=l"(d) : "l"(a), "l"(b), "l"(c));
    return d;
}

// ---------------- kernel 1: umlp + winner + histpos (fused) ----------------
__global__ void fused1_kernel(const float* __restrict__ feat,
                              const float* __restrict__ l1w, const float* __restrict__ l1b,
                              const float* __restrict__ l2w, const float* __restrict__ l2b,
                              const int* __restrict__ user_idx,
                              const int* __restrict__ lap_row) {
    __shared__ float h[32];
    __shared__ float f[4];
    int b = blockIdx.x, t = threadIdx.x;
    if (b < BATCH) {
        if (t < 4) f[t] = feat[b * 4 + t];
        __syncthreads();
        if (t < 32) {
            float s = l1b[t];
#pragma unroll
            for (int i = 0; i < 4; i++) s = fmaf(f[i], l1w[i * 32 + t], s);
            h[t] = s;
        }
        __syncthreads();
        if (t < 64) {
            float s = l2b[t];
#pragma unroll
            for (int k = 0; k < 32; k++) s = fmaf(h[k], l2w[k * 64 + t], s);
            g_umlp[b * 64 + t] = s;
        }
        if (t == 0) atomicMax(&g_winner[user_idx[b]], b + 1);
    }
    int e = b * 256 + t;
    if (e < NNZ) g_pos[e] = atomicAdd(&g_cnt[lap_row[e]], 1);
}

// ---------------- kernel 2/3: scan ----------------
__global__ void blockscan_kernel() {
    __shared__ int wsum[32];
    int t = threadIdx.x, lane = t & 31, wid = t >> 5;
    int i = blockIdx.x * SCANB + t;
    int v = (i < NTOT) ? g_cnt[i] : 0;
#pragma unroll
    for (int o = 1; o < 32; o <<= 1) {
        int n = __shfl_up_sync(0xffffffffu, v, o);
        if (lane >= o) v += n;
    }
    if (lane == 31) wsum[wid] = v;
    __syncthreads();
    if (wid == 0) {
        int s = wsum[lane];
#pragma unroll
        for (int o = 1; o < 32; o <<= 1) {
            int n = __shfl_up_sync(0xffffffffu, s, o);
            if (lane >= o) s += n;
        }
        wsum[lane] = s;
    }
    __syncthreads();
    int incl = v + (wid ? wsum[wid - 1] : 0);
    if (i < NTOT) g_cnt[i] = incl;
    if (t == SCANB - 1) g_bsum[blockIdx.x] = incl;
}

__global__ void topscan_kernel() {
    __shared__ int s[256];
    int t = threadIdx.x;
    int v = (t < NBLK) ? g_bsum[t] : 0;
    s[t] = v;
    __syncthreads();
#pragma unroll
    for (int o = 1; o < 256; o <<= 1) {
        int add = (t >= o) ? s[t - o] : 0;
        __syncthreads();
        s[t] += add;
        __syncthreads();
    }
    if (t < NBLK) g_boff[t] = s[t] - v;   // exclusive
}

// ---------------- kernel 4: initE + finalize rowptr + reset g_cnt ----------------
__global__ void initE_kernel(const float* __restrict__ user_emb,
                             const float* __restrict__ item_emb,
                             const float* __restrict__ ratio_p) {
    int gid = blockIdx.x * blockDim.x + threadIdx.x;
    if (gid < NTOT) {
        g_rowptr[gid + 1] = g_cnt[gid] + g_boff[gid >> 10];
        g_cnt[gid] = 0;
        if (gid == 0) g_rowptr[0] = 0;
    }
    if (gid >= NTOT * 16) return;
    int node = gid >> 4, c = gid & 15;
    float4 v;
    if (node < N_USER) {
        v = reinterpret_cast<const float4*>(user_emb)[node * 16 + c];
        int w = g_winner[node] - 1;
        if (w >= 0) {
            float r = *ratio_p;
            float4 m = reinterpret_cast<const float4*>(g_umlp)[w * 16 + c];
            v.x = v.x * (1.0f - r) + m.x * r;
            v.y = v.y * (1.0f - r) + m.y * r;
            v.z = v.z * (1.0f - r) + m.z * r;
            v.w = v.w * (1.0f - r) + m.w * r;
        }
    } else {
        v = reinterpret_cast<const float4*>(item_emb)[(node - N_USER) * 16 + c];
    }
    reinterpret_cast<float4*>(g_Ebuf[0])[(size_t)node * 16 + c] = v;
    __half2 h01 = __floats2half2_rn(v.x, v.y);
    __half2 h23 = __floats2half2_rn(v.z, v.w);
    uint2 hp;
    hp.x = *reinterpret_cast<unsigned*>(&h01);
    hp.y = *reinterpret_cast<unsigned*>(&h23);
    reinterpret_cast<uint2*>(g_Eh[0])[(size_t)node * 16 + c] = hp;
}

// ---------------- kernel 5: place edges (val pre-dup'd to half2) + reset g_winner ----------------
__global__ void place_kernel(const int* __restrict__ lap_row,
                             const int* __restrict__ lap_col,
                             const float* __restrict__ lap_val) {
    int e = blockIdx.x * blockDim.x + threadIdx.x;
    if (e < NNZ) {
        int r = lap_row[e];
        int p = g_rowptr[r] + g_pos[e];
        __half2 hv = __float2half2_rn(lap_val[e]);
        g_ev[p] = make_int2(lap_col[e], *reinterpret_cast<int*>(&hv));
    }
    if (e < N_USER) g_winner[e] = 0;
}

// ---------------- layer: SpMM (fp16 gather, HFMA2 chunks) + dual GEMM + leaky ----------------
__global__ void __launch_bounds__(256) layer_kernel(int kin,
                                                    const float* __restrict__ w1g,
                                                    const float* __restrict__ b1g,
                                                    const float* __restrict__ w2g,
                                                    const float* __restrict__ b2g,
                                                    int last) {
    __shared__ __align__(16) float wbuf[D * D];                  // 16 KB, w1 then w2
    __shared__ __align__(16) float lie_s[32 * ASTRIDE];          // 8.7 KB
    __shared__ __align__(16) float lee_s[32 * ASTRIDE];          // 8.7 KB
    __shared__ __align__(16) int2  ebuf[8][32];                  // 2 KB edge staging

    const float*    __restrict__ Ein   = g_Ebuf[kin];
    float*          __restrict__ Eout  = g_Ebuf[kin + 1];
    const unsigned* __restrict__ Ehin  = g_Eh[kin & 1];
    unsigned*       __restrict__ Ehout = g_Eh[(kin + 1) & 1];

    int tid = threadIdx.x;
    int lane = tid & 31, warp = tid >> 5;
    int rbase = blockIdx.x * 32;

    // stage w1 while SpMM runs
    for (int i = tid; i < D * D / 4; i += 256)
        reinterpret_cast<float4*>(wbuf)[i] = reinterpret_cast<const float4*>(w1g)[i];

    // ---- phase 1: SpMM. warp handles 4 rows; lane owns feature cols {2*lane, 2*lane+1}
    const float2* __restrict__ E2 = reinterpret_cast<const float2*>(Ein);
    const __half2 hzero = __float2half2_rn(0.f);
#pragma unroll
    for (int rr = 0; rr < 4; rr++) {
        int lrow = warp * 4 + rr;
        int row = rbase + lrow;
        float a0 = 0.f, a1 = 0.f;
        float2 er = make_float2(0.f, 0.f);
        if (row < NTOT) {
            er = E2[(size_t)row * 32 + lane];   // own row, fp32, independent load
            int s = g_rowptr[row], e = g_rowptr[row + 1];
            for (int b0 = s; b0 < e; b0 += 32) {
                int idx = b0 + lane;
                if (idx < e) ebuf[warp][lane] = g_ev[idx];
                __syncwarp();
                int m = e - b0; if (m > 32) m = 32;
                __half2 hacc = hzero;
                int j = 0;
                for (; j + 4 <= m; j += 4) {
                    int2 e0 = ebuf[warp][j + 0];
                    int2 e1 = ebuf[warp][j + 1];
                    int2 e2v = ebuf[warp][j + 2];
                    int2 e3 = ebuf[warp][j + 3];
                    unsigned h0 = Ehin[(size_t)e0.x * 32 + lane];
                    unsigned h1 = Ehin[(size_t)e1.x * 32 + lane];
                    unsigned h2 = Ehin[(size_t)e2v.x * 32 + lane];
                    unsigned h3 = Ehin[(size_t)e3.x * 32 + lane];
                    hacc = __hfma2(*reinterpret_cast<__half2*>(&e0.y),
                                   *reinterpret_cast<__half2*>(&h0), hacc);
                    hacc = __hfma2(*reinterpret_cast<__half2*>(&e1.y),
                                   *reinterpret_cast<__half2*>(&h1), hacc);
                    hacc = __hfma2(*reinterpret_cast<__half2*>(&e2v.y),
                                   *reinterpret_cast<__half2*>(&h2), hacc);
                    hacc = __hfma2(*reinterpret_cast<__half2*>(&e3.y),
                                   *reinterpret_cast<__half2*>(&h3), hacc);
                }
                for (; j < m; j++) {
                    int2 ej = ebuf[warp][j];
                    unsigned hr = Ehin[(size_t)ej.x * 32 + lane];
                    hacc = __hfma2(*reinterpret_cast<__half2*>(&ej.y),
                                   *reinterpret_cast<__half2*>(&hr), hacc);
                }
                float2 fa = __half22float2(hacc);   // flush chunk to fp32
                a0 += fa.x;
                a1 += fa.y;
                __syncwarp();
            }
        }
        float2* dl = reinterpret_cast<float2*>(&lie_s[lrow * ASTRIDE + 2 * lane]);
        float2* dg = reinterpret_cast<float2*>(&lee_s[lrow * ASTRIDE + 2 * lane]);
        *dl = make_float2(a0 + er.x, a1 + er.y);   // (L+I)E
        *dg = make_float2(a0 * er.x, a1 * er.y);   // LE .* E
    }
    __syncthreads();

    // ---- phase 2: block GEMM (conflict-free wbuf[k][j], direct ull2 w loads)
    int rowg = tid >> 4, colg = tid & 15;
    int r0 = 2 * rowg, r1 = r0 + 1;
    int c0 = 4 * colg;

    unsigned long long acc0a, acc0b, acc1a, acc1b;
    {
        float4 bv1 = reinterpret_cast<const float4*>(b1g)[colg];
        float4 bv2 = reinterpret_cast<const float4*>(b2g)[colg];
        acc0a = pack2(bv1.x + bv2.x, bv1.y + bv2.y);
        acc0b = pack2(bv1.z + bv2.z, bv1.w + bv2.w);
        acc1a = acc0a; acc1b = acc0b;
    }

#pragma unroll 4
    for (int k0 = 0; k0 < D; k0 += 4) {
        float4 aA = *reinterpret_cast<const float4*>(&lie_s[r0 * ASTRIDE + k0]);
        float4 aB = *reinterpret_cast<const float4*>(&lie_s[r1 * ASTRIDE + k0]);
#pragma unroll
        for (int kk = 0; kk < 4; kk++) {
            ulonglong2 wv = *reinterpret_cast<const ulonglong2*>(&wbuf[(k0 + kk) * D + c0]);
            unsigned long long dA = pack_dup((&aA.x)[kk]);
            unsigned long long dB = pack_dup((&aB.x)[kk]);
            acc0a = ffma2(dA, wv.x, acc0a);
            acc0b = ffma2(dA, wv.y, acc0b);
            acc1a = ffma2(dB, wv.x, acc1a);
            acc1b = ffma2(dB, wv.y, acc1b);
        }
    }
    __syncthreads();

    // reload weight buffer with w2
    for (int i = tid; i < D * D / 4; i += 256)
        reinterpret_cast<float4*>(wbuf)[i] = reinterpret_cast<const float4*>(w2g)[i];
    __syncthreads();

#pragma unroll 4
    for (int k0 = 0; k0 < D; k0 += 4) {
        float4 aA = *reinterpret_cast<const float4*>(&lee_s[r0 * ASTRIDE + k0]);
        float4 aB = *reinterpret_cast<const float4*>(&lee_s[r1 * ASTRIDE + k0]);
#pragma unroll
        for (int kk = 0; kk < 4; kk++) {
            ulonglong2 wv = *reinterpret_cast<const ulonglong2*>(&wbuf[(k0 + kk) * D + c0]);
            unsigned long long dA = pack_dup((&aA.x)[kk]);
            unsigned long long dB = pack_dup((&aB.x)[kk]);
            acc0a = ffma2(dA, wv.x, acc0a);
            acc0b = ffma2(dA, wv.y, acc0b);
            acc1a = ffma2(dB, wv.x, acc1a);
            acc1b = ffma2(dB, wv.y, acc1b);
        }
    }

    // ---- epilogue: leaky relu + stores (norm deferred to out_kernel)
    float2 o0a = unpack2(acc0a), o0b = unpack2(acc0b);
    float2 o1a = unpack2(acc1a), o1b = unpack2(acc1b);
    o0a.x = o0a.x >= 0.f ? o0a.x : 0.2f * o0a.x;
    o0a.y = o0a.y >= 0.f ? o0a.y : 0.2f * o0a.y;
    o0b.x = o0b.x >= 0.f ? o0b.x : 0.2f * o0b.x;
    o0b.y = o0b.y >= 0.f ? o0b.y : 0.2f * o0b.y;
    o1a.x = o1a.x >= 0.f ? o1a.x : 0.2f * o1a.x;
    o1a.y = o1a.y >= 0.f ? o1a.y : 0.2f * o1a.y;
    o1b.x = o1b.x >= 0.f ? o1b.x : 0.2f * o1b.x;
    o1b.y = o1b.y >= 0.f ? o1b.y : 0.2f * o1b.y;

    int grow0 = rbase + r0, grow1 = rbase + r1;
    float4* EoutV = reinterpret_cast<float4*>(Eout);
    uint2* EhV = reinterpret_cast<uint2*>(Ehout);

    if (grow0 < NTOT) {
        float4 w = make_float4(o0a.x, o0a.y, o0b.x, o0b.y);
        EoutV[(size_t)grow0 * 16 + colg] = w;
        if (!last) {
            __half2 h01 = __floats2half2_rn(w.x, w.y);
            __half2 h23 = __floats2half2_rn(w.z, w.w);
            uint2 hp;
            hp.x = *reinterpret_cast<unsigned*>(&h01);
            hp.y = *reinterpret_cast<unsigned*>(&h23);
            EhV[(size_t)grow0 * 16 + colg] = hp;
        }
    }
    if (grow1 < NTOT) {
        float4 w = make_float4(o1a.x, o1a.y, o1b.x, o1b.y);
        EoutV[(size_t)grow1 * 16 + colg] = w;
        if (!last) {
            __half2 h01 = __floats2half2_rn(w.x, w.y);
            __half2 h23 = __floats2half2_rn(w.z, w.w);
            uint2 hp;
            hp.x = *reinterpret_cast<unsigned*>(&h01);
            hp.y = *reinterpret_cast<unsigned*>(&h23);
            EhV[(size_t)grow1 * 16 + colg] = hp;
        }
    }
}

// ---------------- final gather + deferred normalization ----------------
__global__ void out_kernel(const int* __restrict__ uidx,
                           const int* __restrict__ pidx,
                           const int* __restrict__ nidx,
                           float* __restrict__ out) {
    int warp = threadIdx.x >> 5, lane = threadIdx.x & 31;
    int g = blockIdx.x * 8 + warp;            // 0..3071
    int b = g & (BATCH - 1);
    int which = g >> 10;
    int row;
    if (which == 0) row = uidx[b];
    else if (which == 1) row = N_USER + pidx[b];
    else row = N_USER + nidx[b];

    float2* dst = reinterpret_cast<float2*>(out) + (size_t)g * 128;
#pragma unroll
    for (int k = 0; k < 4; k++) {
        float2 v = reinterpret_cast<const float2*>(g_Ebuf[k])[(size_t)row * 32 + lane];
        float sc = 1.0f;
        if (k > 0) {
            float ss = v.x * v.x + v.y * v.y;
#pragma unroll
            for (int o = 16; o > 0; o >>= 1) ss += __shfl_xor_sync(0xffffffffu, ss, o);
            sc = 1.0f / fmaxf(sqrtf(ss), 1e-12f);
        }
        dst[k * 32 + lane] = make_float2(v.x * sc, v.y * sc);
    }
}

// ---------------- launch ----------------
extern "C" void kernel_launch(void* const* d_in, const int* in_sizes, int n_in,
                              void* d_out, int out_size) {
    int iUE, iIE, iUF, iL1W, iL1B, iL2W, iL2B, iW1, iB1, iW2, iB2, iLV, iR, iLR, iLC, iUI, iPI, iNI;
    if (n_in >= 18 && in_sizes[2] == 4096) {
        iUE = 0; iIE = 1; iUF = 2; iL1W = 3; iL1B = 4; iL2W = 5; iL2B = 6;
        iW1 = 7; iB1 = 8; iW2 = 9; iB2 = 10; iLV = 11; iR = 12; iLR = 13; iLC = 14;
        iUI = 15; iPI = 16; iNI = 17;
    } else {
        iUE = 0; iIE = 1; iL1W = 2; iL1B = 3; iL2W = 4; iL2B = 5;
        iW1 = 6; iB1 = 7; iW2 = 8; iB2 = 9; iLR = 10; iLC = 11; iLV = 12;
        iUI = 13; iUF = 14; iPI = 15; iNI = 16; iR = 17;
    }

    const float* user_emb = (const float*)d_in[iUE];
    const float* item_emb = (const float*)d_in[iIE];
    const float* user_feat = (const float*)d_in[iUF];
    const float* lin1_w = (const float*)d_in[iL1W];
    const float* lin1_b = (const float*)d_in[iL1B];
    const float* lin2_w = (const float*)d_in[iL2W];
    const float* lin2_b = (const float*)d_in[iL2B];
    const float* w1 = (const float*)d_in[iW1];
    const float* b1 = (const float*)d_in[iB1];
    const float* w2 = (const float*)d_in[iW2];
    const float* b2 = (const float*)d_in[iB2];
    const float* lap_val = (const float*)d_in[iLV];
    const float* ratio = (const float*)d_in[iR];
    const int* lap_row = (const int*)d_in[iLR];
    const int* lap_col = (const int*)d_in[iLC];
    const int* user_idx = (const int*)d_in[iUI];
    const int* pos_idx = (const int*)d_in[iPI];
    const int* neg_idx = (const int*)d_in[iNI];

    // 1: user MLP + winner + edge histogram/position (one pass)
    fused1_kernel<<<(NNZ + 255) / 256, 256>>>(user_feat, lin1_w, lin1_b, lin2_w, lin2_b,
                                              user_idx, lap_row);
    // 2-3: scan
    blockscan_kernel<<<NBLK, SCANB>>>();
    topscan_kernel<<<1, 256>>>();
    // 4: E0 init (+ finalize rowptr, reset g_cnt)
    initE_kernel<<<(NTOT * 16 + 255) / 256, 256>>>(user_emb, item_emb, ratio);
    // 5: place edges (+ reset g_winner)
    place_kernel<<<(NNZ + 255) / 256, 256>>>(lap_row, lap_col, lap_val);

    // 6-8: 3 fused graph-conv layers
    for (int k = 0; k < NLAY; k++) {
        layer_kernel<<<(NTOT + 31) / 32, 256>>>(k,
                                                w1 + k * D * D, b1 + k * D,
                                                w2 + k * D * D, b2 + k * D,
                                                k == NLAY - 1);
    }

    // 9: gather + deferred normalization
    out_kernel<<<3 * BATCH / 8, 256>>>(user_idx, pos_idx, neg_idx, (float*)d_out);
}

// round 9
// speedup vs baseline: 3.3456x; 1.2924x over previous
#include <cuda_runtime.h>
#include <cuda_fp16.h>

#define N_USER 50000
#define N_ITEM 100000
#define NTOT   150000
#define D      64
#define NLAY   3
#define NNZ    2400000
#define BATCH  1024
#define SCANB  1024
#define NBLK   ((NTOT + SCANB - 1) / SCANB)   // 147
#define AST    132                            // acat row stride (uints): conflict-free A frags
#define WST    72                             // wbuf row stride (uints): conflict-free B frags

// ---------------- scratch (static device globals; no allocation) ----------------
__device__ int      g_rowptr[NTOT + 1];
__device__ int      g_cnt[NTOT];              // zero at load; re-zeroed each call
__device__ int      g_pos[NNZ];
__device__ int      g_bsum[NBLK + 16];
__device__ int      g_boff[NBLK + 16];
__device__ int2     g_ev[NNZ];                // packed (col, half2(val,val))
__device__ float    g_Ebuf[4][(size_t)NTOT * D];         // E0, L1, L2, L3 (unnormalized, post-act)
__device__ unsigned g_Eh[2][(size_t)NTOT * 32];          // fp16x2 ping-pong (gather reads)
__device__ float    g_umlp[BATCH * D];
__device__ int      g_winner[N_USER];         // 0 = none, else batch_idx+1; reset each call

// ---------------- tf32 / mma helpers ----------------
__device__ __forceinline__ unsigned tf32cvt(float f) {
    unsigned r;
    asm("cvt.rna.tf32.f32 %0, %1;" : "=r"(r) : "f"(f));
    return r;
}
__device__ __forceinline__ void mma_tf32(float* d,
                                         unsigned a0, unsigned a1, unsigned a2, unsigned a3,
                                         unsigned b0, unsigned b1) {
    asm volatile("mma.sync.aligned.m16n8k8.row.col.f32.tf32.tf32.f32 "
                 "{%0,%1,%2,%3},{%4,%5,%6,%7},{%8,%9},{%0,%1,%2,%3};"
                 : "+f"(d[0]), "+f"(d[1]), "+f"(d[2]), "+f"(d[3])
                 : "r"(a0), "r"(a1), "r"(a2), "r"(a3), "r"(b0), "r"(b1));
}

// ---------------- kernel 1: umlp + winner + histpos (fused) ----------------
__global__ void fused1_kernel(const float* __restrict__ feat,
                              const float* __restrict__ l1w, const float* __restrict__ l1b,
                              const float* __restrict__ l2w, const float* __restrict__ l2b,
                              const int* __restrict__ user_idx,
                              const int* __restrict__ lap_row) {
    __shared__ float h[32];
    __shared__ float f[4];
    int b = blockIdx.x, t = threadIdx.x;
    if (b < BATCH) {
        if (t < 4) f[t] = feat[b * 4 + t];
        __syncthreads();
        if (t < 32) {
            float s = l1b[t];
#pragma unroll
            for (int i = 0; i < 4; i++) s = fmaf(f[i], l1w[i * 32 + t], s);
            h[t] = s;
        }
        __syncthreads();
        if (t < 64) {
            float s = l2b[t];
#pragma unroll
            for (int k = 0; k < 32; k++) s = fmaf(h[k], l2w[k * 64 + t], s);
            g_umlp[b * 64 + t] = s;
        }
        if (t == 0) atomicMax(&g_winner[user_idx[b]], b + 1);
    }
    int e = b * 256 + t;
    if (e < NNZ) g_pos[e] = atomicAdd(&g_cnt[lap_row[e]], 1);
}

// ---------------- kernel 2/3: scan ----------------
__global__ void blockscan_kernel() {
    __shared__ int wsum[32];
    int t = threadIdx.x, lane = t & 31, wid = t >> 5;
    int i = blockIdx.x * SCANB + t;
    int v = (i < NTOT) ? g_cnt[i] : 0;
#pragma unroll
    for (int o = 1; o < 32; o <<= 1) {
        int n = __shfl_up_sync(0xffffffffu, v, o);
        if (lane >= o) v += n;
    }
    if (lane == 31) wsum[wid] = v;
    __syncthreads();
    if (wid == 0) {
        int s = wsum[lane];
#pragma unroll
        for (int o = 1; o < 32; o <<= 1) {
            int n = __shfl_up_sync(0xffffffffu, s, o);
            if (lane >= o) s += n;
        }
        wsum[lane] = s;
    }
    __syncthreads();
    int incl = v + (wid ? wsum[wid - 1] : 0);
    if (i < NTOT) g_cnt[i] = incl;
    if (t == SCANB - 1) g_bsum[blockIdx.x] = incl;
}

__global__ void topscan_kernel() {
    __shared__ int s[256];
    int t = threadIdx.x;
    int v = (t < NBLK) ? g_bsum[t] : 0;
    s[t] = v;
    __syncthreads();
#pragma unroll
    for (int o = 1; o < 256; o <<= 1) {
        int add = (t >= o) ? s[t - o] : 0;
        __syncthreads();
        s[t] += add;
        __syncthreads();
    }
    if (t < NBLK) g_boff[t] = s[t] - v;   // exclusive
}

// ---------------- kernel 4: initE + finalize rowptr + reset g_cnt ----------------
__global__ void initE_kernel(const float* __restrict__ user_emb,
                             const float* __restrict__ item_emb,
                             const float* __restrict__ ratio_p) {
    int gid = blockIdx.x * blockDim.x + threadIdx.x;
    if (gid < NTOT) {
        g_rowptr[gid + 1] = g_cnt[gid] + g_boff[gid >> 10];
        g_cnt[gid] = 0;
        if (gid == 0) g_rowptr[0] = 0;
    }
    if (gid >= NTOT * 16) return;
    int node = gid >> 4, c = gid & 15;
    float4 v;
    if (node < N_USER) {
        v = reinterpret_cast<const float4*>(user_emb)[node * 16 + c];
        int w = g_winner[node] - 1;
        if (w >= 0) {
            float r = *ratio_p;
            float4 m = reinterpret_cast<const float4*>(g_umlp)[w * 16 + c];
            v.x = v.x * (1.0f - r) + m.x * r;
            v.y = v.y * (1.0f - r) + m.y * r;
            v.z = v.z * (1.0f - r) + m.z * r;
            v.w = v.w * (1.0f - r) + m.w * r;
        }
    } else {
        v = reinterpret_cast<const float4*>(item_emb)[(node - N_USER) * 16 + c];
    }
    reinterpret_cast<float4*>(g_Ebuf[0])[(size_t)node * 16 + c] = v;
    __half2 h01 = __floats2half2_rn(v.x, v.y);
    __half2 h23 = __floats2half2_rn(v.z, v.w);
    uint2 hp;
    hp.x = *reinterpret_cast<unsigned*>(&h01);
    hp.y = *reinterpret_cast<unsigned*>(&h23);
    reinterpret_cast<uint2*>(g_Eh[0])[(size_t)node * 16 + c] = hp;
}

// ---------------- kernel 5: place edges (val pre-dup'd to half2) + reset g_winner ----------------
__global__ void place_kernel(const int* __restrict__ lap_row,
                             const int* __restrict__ lap_col,
                             const float* __restrict__ lap_val) {
    int e = blockIdx.x * blockDim.x + threadIdx.x;
    if (e < NNZ) {
        int r = lap_row[e];
        int p = g_rowptr[r] + g_pos[e];
        __half2 hv = __float2half2_rn(lap_val[e]);
        g_ev[p] = make_int2(lap_col[e], *reinterpret_cast<int*>(&hv));
    }
    if (e < N_USER) g_winner[e] = 0;
}

// ---------------- layer: SpMM (fp16 gather, HFMA2) + tf32 tensor-core dual GEMM ----------------
__global__ void __launch_bounds__(256) layer_kernel(int kin,
                                                    const float* __restrict__ w1g,
                                                    const float* __restrict__ b1g,
                                                    const float* __restrict__ w2g,
                                                    const float* __restrict__ b2g,
                                                    int last) {
    __shared__ __align__(16) unsigned acat[32 * AST];   // tf32 A: cols 0-63 lie, 64-127 lee (16.9 KB)
    __shared__ __align__(16) unsigned wbuf[64 * WST];   // tf32 weights, w1 then w2 (18.4 KB)
    __shared__ __align__(16) int2     ebuf[8][32];      // 2 KB edge staging

    const float*    __restrict__ Ein   = g_Ebuf[kin];
    float*          __restrict__ Eout  = g_Ebuf[kin + 1];
    const unsigned* __restrict__ Ehin  = g_Eh[kin & 1];
    unsigned*       __restrict__ Ehout = g_Eh[(kin + 1) & 1];

    int tid = threadIdx.x;
    int lane = tid & 31, warp = tid >> 5;
    int rbase = blockIdx.x * 32;

    // stage w1 (tf32) while SpMM runs
    for (int i = tid; i < D * D / 4; i += 256) {
        float4 wv = reinterpret_cast<const float4*>(w1g)[i];
        int k = i >> 4, j = (i & 15) * 4;
        unsigned* dst = &wbuf[k * WST + j];
        dst[0] = tf32cvt(wv.x); dst[1] = tf32cvt(wv.y);
        dst[2] = tf32cvt(wv.z); dst[3] = tf32cvt(wv.w);
    }

    // ---- phase 1: SpMM. warp handles 4 rows; lane owns feature cols {2*lane, 2*lane+1}
    const float2* __restrict__ E2 = reinterpret_cast<const float2*>(Ein);
    const __half2 hzero = __float2half2_rn(0.f);
#pragma unroll
    for (int rr = 0; rr < 4; rr++) {
        int lrow = warp * 4 + rr;
        int row = rbase + lrow;
        float a0 = 0.f, a1 = 0.f;
        float2 er = make_float2(0.f, 0.f);
        if (row < NTOT) {
            er = E2[(size_t)row * 32 + lane];
            int s = g_rowptr[row], e = g_rowptr[row + 1];
            for (int b0 = s; b0 < e; b0 += 32) {
                int idx = b0 + lane;
                if (idx < e) ebuf[warp][lane] = g_ev[idx];
                __syncwarp();
                int m = e - b0; if (m > 32) m = 32;
                __half2 hacc = hzero;
                int j = 0;
                for (; j + 4 <= m; j += 4) {
                    int2 e0 = ebuf[warp][j + 0];
                    int2 e1 = ebuf[warp][j + 1];
                    int2 e2v = ebuf[warp][j + 2];
                    int2 e3 = ebuf[warp][j + 3];
                    unsigned h0 = Ehin[(size_t)e0.x * 32 + lane];
                    unsigned h1 = Ehin[(size_t)e1.x * 32 + lane];
                    unsigned h2 = Ehin[(size_t)e2v.x * 32 + lane];
                    unsigned h3 = Ehin[(size_t)e3.x * 32 + lane];
                    hacc = __hfma2(*reinterpret_cast<__half2*>(&e0.y),
                                   *reinterpret_cast<__half2*>(&h0), hacc);
                    hacc = __hfma2(*reinterpret_cast<__half2*>(&e1.y),
                                   *reinterpret_cast<__half2*>(&h1), hacc);
                    hacc = __hfma2(*reinterpret_cast<__half2*>(&e2v.y),
                                   *reinterpret_cast<__half2*>(&h2), hacc);
                    hacc = __hfma2(*reinterpret_cast<__half2*>(&e3.y),
                                   *reinterpret_cast<__half2*>(&h3), hacc);
                }
                for (; j < m; j++) {
                    int2 ej = ebuf[warp][j];
                    unsigned hr = Ehin[(size_t)ej.x * 32 + lane];
                    hacc = __hfma2(*reinterpret_cast<__half2*>(&ej.y),
                                   *reinterpret_cast<__half2*>(&hr), hacc);
                }
                float2 fa = __half22float2(hacc);   // flush chunk to fp32
                a0 += fa.x;
                a1 += fa.y;
                __syncwarp();
            }
        }
        // write tf32 A tile: lie at cols 2lane..+1, lee at 64+2lane..+1
        uint2 lie = make_uint2(tf32cvt(a0 + er.x), tf32cvt(a1 + er.y));
        uint2 lee = make_uint2(tf32cvt(a0 * er.x), tf32cvt(a1 * er.y));
        *reinterpret_cast<uint2*>(&acat[lrow * AST + 2 * lane]) = lie;
        *reinterpret_cast<uint2*>(&acat[lrow * AST + 64 + 2 * lane]) = lee;
    }
    __syncthreads();

    // ---- phase 2: tensor-core GEMM. warp -> n-octet n0 = warp*8; tiles m0 in {0,16}
    int n0 = warp * 8;
    int fr = lane >> 2, fc = lane & 3;
    float acc[2][4] = {{0.f, 0.f, 0.f, 0.f}, {0.f, 0.f, 0.f, 0.f}};

    // pass 1: A = lie (cols 0-63), B = w1
#pragma unroll
    for (int t = 0; t < 2; t++) {
        int m0 = t * 16;
#pragma unroll
        for (int k0 = 0; k0 < 64; k0 += 8) {
            const unsigned* A = &acat[(m0 + fr) * AST + k0 + fc];
            unsigned a0 = A[0], a1 = A[8 * AST], a2 = A[4], a3 = A[8 * AST + 4];
            const unsigned* B = &wbuf[(k0 + fc) * WST + n0 + fr];
            unsigned b0 = B[0], b1 = B[4 * WST];
            mma_tf32(acc[t], a0, a1, a2, a3, b0, b1);
        }
    }
    __syncthreads();

    // restage w2
    for (int i = tid; i < D * D / 4; i += 256) {
        float4 wv = reinterpret_cast<const float4*>(w2g)[i];
        int k = i >> 4, j = (i & 15) * 4;
        unsigned* dst = &wbuf[k * WST + j];
        dst[0] = tf32cvt(wv.x); dst[1] = tf32cvt(wv.y);
        dst[2] = tf32cvt(wv.z); dst[3] = tf32cvt(wv.w);
    }
    __syncthreads();

    // pass 2: A = lee (cols 64-127), B = w2, accumulate
#pragma unroll
    for (int t = 0; t < 2; t++) {
        int m0 = t * 16;
#pragma unroll
        for (int k0 = 0; k0 < 64; k0 += 8) {
            const unsigned* A = &acat[(m0 + fr) * AST + 64 + k0 + fc];
            unsigned a0 = A[0], a1 = A[8 * AST], a2 = A[4], a3 = A[8 * AST + 4];
            const unsigned* B = &wbuf[(k0 + fc) * WST + n0 + fr];
            unsigned b0 = B[0], b1 = B[4 * WST];
            mma_tf32(acc[t], a0, a1, a2, a3, b0, b1);
        }
    }

    // ---- epilogue: bias + leaky + stores (fragment layout: c0/c1 row fr, c2/c3 row fr+8)
    int cb = n0 + 2 * fc;
    float2 bias = make_float2(b1g[cb] + b2g[cb], b1g[cb + 1] + b2g[cb + 1]);
    float2* EoutV = reinterpret_cast<float2*>(Eout);
    unsigned* EhV = Ehout;
    int colp = (n0 >> 1) + fc;   // float2 column index
#pragma unroll
    for (int t = 0; t < 2; t++) {
#pragma unroll
        for (int h = 0; h < 2; h++) {
            int grow = rbase + t * 16 + fr + h * 8;
            if (grow < NTOT) {
                float vx = acc[t][2 * h] + bias.x;
                float vy = acc[t][2 * h + 1] + bias.y;
                vx = vx >= 0.f ? vx : 0.2f * vx;
                vy = vy >= 0.f ? vy : 0.2f * vy;
                EoutV[(size_t)grow * 32 + colp] = make_float2(vx, vy);
                if (!last) {
                    __half2 hv = __floats2half2_rn(vx, vy);
                    EhV[(size_t)grow * 32 + colp] = *reinterpret_cast<unsigned*>(&hv);
                }
            }
        }
    }
}

// ---------------- final gather + deferred normalization ----------------
__global__ void out_kernel(const int* __restrict__ uidx,
                           const int* __restrict__ pidx,
                           const int* __restrict__ nidx,
                           float* __restrict__ out) {
    int warp = threadIdx.x >> 5, lane = threadIdx.x & 31;
    int g = blockIdx.x * 8 + warp;            // 0..3071
    int b = g & (BATCH - 1);
    int which = g >> 10;
    int row;
    if (which == 0) row = uidx[b];
    else if (which == 1) row = N_USER + pidx[b];
    else row = N_USER + nidx[b];

    float2* dst = reinterpret_cast<float2*>(out) + (size_t)g * 128;
#pragma unroll
    for (int k = 0; k < 4; k++) {
        float2 v = reinterpret_cast<const float2*>(g_Ebuf[k])[(size_t)row * 32 + lane];
        float sc = 1.0f;
        if (k > 0) {
            float ss = v.x * v.x + v.y * v.y;
#pragma unroll
            for (int o = 16; o > 0; o >>= 1) ss += __shfl_xor_sync(0xffffffffu, ss, o);
            sc = 1.0f / fmaxf(sqrtf(ss), 1e-12f);
        }
        dst[k * 32 + lane] = make_float2(v.x * sc, v.y * sc);
    }
}

// ---------------- launch ----------------
extern "C" void kernel_launch(void* const* d_in, const int* in_sizes, int n_in,
                              void* d_out, int out_size) {
    int iUE, iIE, iUF, iL1W, iL1B, iL2W, iL2B, iW1, iB1, iW2, iB2, iLV, iR, iLR, iLC, iUI, iPI, iNI;
    if (n_in >= 18 && in_sizes[2] == 4096) {
        iUE = 0; iIE = 1; iUF = 2; iL1W = 3; iL1B = 4; iL2W = 5; iL2B = 6;
        iW1 = 7; iB1 = 8; iW2 = 9; iB2 = 10; iLV = 11; iR = 12; iLR = 13; iLC = 14;
        iUI = 15; iPI = 16; iNI = 17;
    } else {
        iUE = 0; iIE = 1; iL1W = 2; iL1B = 3; iL2W = 4; iL2B = 5;
        iW1 = 6; iB1 = 7; iW2 = 8; iB2 = 9; iLR = 10; iLC = 11; iLV = 12;
        iUI = 13; iUF = 14; iPI = 15; iNI = 16; iR = 17;
    }

    const float* user_emb = (const float*)d_in[iUE];
    const float* item_emb = (const float*)d_in[iIE];
    const float* user_feat = (const float*)d_in[iUF];
    const float* lin1_w = (const float*)d_in[iL1W];
    const float* lin1_b = (const float*)d_in[iL1B];
    const float* lin2_w = (const float*)d_in[iL2W];
    const float* lin2_b = (const float*)d_in[iL2B];
    const float* w1 = (const float*)d_in[iW1];
    const float* b1 = (const float*)d_in[iB1];
    const float* w2 = (const float*)d_in[iW2];
    const float* b2 = (const float*)d_in[iB2];
    const float* lap_val = (const float*)d_in[iLV];
    const float* ratio = (const float*)d_in[iR];
    const int* lap_row = (const int*)d_in[iLR];
    const int* lap_col = (const int*)d_in[iLC];
    const int* user_idx = (const int*)d_in[iUI];
    const int* pos_idx = (const int*)d_in[iPI];
    const int* neg_idx = (const int*)d_in[iNI];

    // 1: user MLP + winner + edge histogram/position (one pass)
    fused1_kernel<<<(NNZ + 255) / 256, 256>>>(user_feat, lin1_w, lin1_b, lin2_w, lin2_b,
                                              user_idx, lap_row);
    // 2-3: scan
    blockscan_kernel<<<NBLK, SCANB>>>();
    topscan_kernel<<<1, 256>>>();
    // 4: E0 init (+ finalize rowptr, reset g_cnt)
    initE_kernel<<<(NTOT * 16 + 255) / 256, 256>>>(user_emb, item_emb, ratio);
    // 5: place edges (+ reset g_winner)
    place_kernel<<<(NNZ + 255) / 256, 256>>>(lap_row, lap_col, lap_val);

    // 6-8: 3 fused graph-conv layers
    for (int k = 0; k < NLAY; k++) {
        layer_kernel<<<(NTOT + 31) / 32, 256>>>(k,
                                                w1 + k * D * D, b1 + k * D,
                                                w2 + k * D * D, b2 + k * D,
                                                k == NLAY - 1);
    }

    // 9: gather + deferred normalization
    out_kernel<<<3 * BATCH / 8, 256>>>(user_idx, pos_idx, neg_idx, (float*)d_out);
}

// round 10
// speedup vs baseline: 3.3834x; 1.0113x over previous
#include <cuda_runtime.h>
#include <cuda_fp16.h>

#define N_USER 50000
#define N_ITEM 100000
#define NTOT   150000
#define D      64
#define NLAY   3
#define NNZ    2400000
#define BATCH  1024
#define SCANB  1024
#define NBLK   ((NTOT + SCANB - 1) / SCANB)   // 147
#define AST    132                            // acat row stride (uints): conflict-free A frags

// ---------------- scratch (static device globals; no allocation) ----------------
__device__ int      g_rowptr[NTOT + 1];
__device__ int      g_cnt[NTOT];              // zero at load; re-zeroed each call
__device__ int      g_pos[NNZ];
__device__ int      g_bsum[NBLK + 16];
__device__ int      g_boff[NBLK + 16];
__device__ int2     g_ev[NNZ];                // packed (col, half2(val,val))
__device__ float    g_Ebuf[4][(size_t)NTOT * D];         // E0, L1, L2, L3 (unnormalized, post-act)
__device__ unsigned g_Eh[2][(size_t)NTOT * 32];          // fp16x2 ping-pong (gather reads)
__device__ float    g_umlp[BATCH * D];
__device__ int      g_winner[N_USER];         // 0 = none, else batch_idx+1; reset each call
__device__ unsigned g_wt[NLAY * 2 * D * D];   // tf32 weights: [layer][{w1,w2}][k][j]
__device__ float    g_bias[NLAY * D];         // b1+b2 per layer

// ---------------- tf32 / mma helpers ----------------
__device__ __forceinline__ unsigned tf32cvt(float f) {
    unsigned r;
    asm("cvt.rna.tf32.f32 %0, %1;" : "=r"(r) : "f"(f));
    return r;
}
__device__ __forceinline__ void mma_tf32(float* d,
                                         unsigned a0, unsigned a1, unsigned a2, unsigned a3,
                                         unsigned b0, unsigned b1) {
    asm volatile("mma.sync.aligned.m16n8k8.row.col.f32.tf32.tf32.f32 "
                 "{%0,%1,%2,%3},{%4,%5,%6,%7},{%8,%9},{%0,%1,%2,%3};"
                 : "+f"(d[0]), "+f"(d[1]), "+f"(d[2]), "+f"(d[3])
                 : "r"(a0), "r"(a1), "r"(a2), "r"(a3), "r"(b0), "r"(b1));
}

// ---------------- kernel 1: umlp + winner + histpos + weight cvt (fused) ----------------
__global__ void fused1_kernel(const float* __restrict__ feat,
                              const float* __restrict__ l1w, const float* __restrict__ l1b,
                              const float* __restrict__ l2w, const float* __restrict__ l2b,
                              const int* __restrict__ user_idx,
                              const int* __restrict__ lap_row,
                              const float* __restrict__ w1g, const float* __restrict__ b1g,
                              const float* __restrict__ w2g, const float* __restrict__ b2g) {
    __shared__ float h[32];
    __shared__ float f[4];
    int b = blockIdx.x, t = threadIdx.x;
    if (b < BATCH) {
        if (t < 4) f[t] = feat[b * 4 + t];
        __syncthreads();
        if (t < 32) {
            float s = l1b[t];
#pragma unroll
            for (int i = 0; i < 4; i++) s = fmaf(f[i], l1w[i * 32 + t], s);
            h[t] = s;
        }
        __syncthreads();
        if (t < 64) {
            float s = l2b[t];
#pragma unroll
            for (int k = 0; k < 32; k++) s = fmaf(h[k], l2w[k * 64 + t], s);
            g_umlp[b * 64 + t] = s;
        }
        if (t == 0) atomicMax(&g_winner[user_idx[b]], b + 1);
    } else if (b < BATCH + 96) {
        // tf32 weight table: 3 layers x {w1,w2} x 4096
        int idx = (b - BATCH) * 256 + t;      // 0..24575
        int layer = idx >> 13;
        int rest = idx & 8191;
        const float* src = (rest < 4096) ? w1g : w2g;
        g_wt[idx] = tf32cvt(src[layer * 4096 + (rest & 4095)]);
    } else if (b == BATCH + 96) {
        if (t < NLAY * D) g_bias[t] = b1g[t] + b2g[t];
    }
    int e = b * 256 + t;
    if (e < NNZ) g_pos[e] = atomicAdd(&g_cnt[lap_row[e]], 1);
}

// ---------------- kernel 2/3: scan ----------------
__global__ void blockscan_kernel() {
    __shared__ int wsum[32];
    int t = threadIdx.x, lane = t & 31, wid = t >> 5;
    int i = blockIdx.x * SCANB + t;
    int v = (i < NTOT) ? g_cnt[i] : 0;
#pragma unroll
    for (int o = 1; o < 32; o <<= 1) {
        int n = __shfl_up_sync(0xffffffffu, v, o);
        if (lane >= o) v += n;
    }
    if (lane == 31) wsum[wid] = v;
    __syncthreads();
    if (wid == 0) {
        int s = wsum[lane];
#pragma unroll
        for (int o = 1; o < 32; o <<= 1) {
            int n = __shfl_up_sync(0xffffffffu, s, o);
            if (lane >= o) s += n;
        }
        wsum[lane] = s;
    }
    __syncthreads();
    int incl = v + (wid ? wsum[wid - 1] : 0);
    if (i < NTOT) g_cnt[i] = incl;
    if (t == SCANB - 1) g_bsum[blockIdx.x] = incl;
}

__global__ void topscan_kernel() {
    __shared__ int s[256];
    int t = threadIdx.x;
    int v = (t < NBLK) ? g_bsum[t] : 0;
    s[t] = v;
    __syncthreads();
#pragma unroll
    for (int o = 1; o < 256; o <<= 1) {
        int add = (t >= o) ? s[t - o] : 0;
        __syncthreads();
        s[t] += add;
        __syncthreads();
    }
    if (t < NBLK) g_boff[t] = s[t] - v;   // exclusive
}

// ---------------- kernel 4: initE + finalize rowptr + reset g_cnt ----------------
__global__ void initE_kernel(const float* __restrict__ user_emb,
                             const float* __restrict__ item_emb,
                             const float* __restrict__ ratio_p) {
    int gid = blockIdx.x * blockDim.x + threadIdx.x;
    if (gid < NTOT) {
        g_rowptr[gid + 1] = g_cnt[gid] + g_boff[gid >> 10];
        g_cnt[gid] = 0;
        if (gid == 0) g_rowptr[0] = 0;
    }
    if (gid >= NTOT * 16) return;
    int node = gid >> 4, c = gid & 15;
    float4 v;
    if (node < N_USER) {
        v = reinterpret_cast<const float4*>(user_emb)[node * 16 + c];
        int w = g_winner[node] - 1;
        if (w >= 0) {
            float r = *ratio_p;
            float4 m = reinterpret_cast<const float4*>(g_umlp)[w * 16 + c];
            v.x = v.x * (1.0f - r) + m.x * r;
            v.y = v.y * (1.0f - r) + m.y * r;
            v.z = v.z * (1.0f - r) + m.z * r;
            v.w = v.w * (1.0f - r) + m.w * r;
        }
    } else {
        v = reinterpret_cast<const float4*>(item_emb)[(node - N_USER) * 16 + c];
    }
    reinterpret_cast<float4*>(g_Ebuf[0])[(size_t)node * 16 + c] = v;
    __half2 h01 = __floats2half2_rn(v.x, v.y);
    __half2 h23 = __floats2half2_rn(v.z, v.w);
    uint2 hp;
    hp.x = *reinterpret_cast<unsigned*>(&h01);
    hp.y = *reinterpret_cast<unsigned*>(&h23);
    reinterpret_cast<uint2*>(g_Eh[0])[(size_t)node * 16 + c] = hp;
}

// ---------------- kernel 5: place edges (val pre-dup'd to half2) + reset g_winner ----------------
__global__ void place_kernel(const int* __restrict__ lap_row,
                             const int* __restrict__ lap_col,
                             const float* __restrict__ lap_val) {
    int e = blockIdx.x * blockDim.x + threadIdx.x;
    if (e < NNZ) {
        int r = lap_row[e];
        int p = g_rowptr[r] + g_pos[e];
        __half2 hv = __float2half2_rn(lap_val[e]);
        g_ev[p] = make_int2(lap_col[e], *reinterpret_cast<int*>(&hv));
    }
    if (e < N_USER) g_winner[e] = 0;
}

// ---------------- layer: SpMM (fp16 gather, HFMA2) + tf32 MMA with gmem B-frags ----------------
__global__ void __launch_bounds__(256) layer_kernel(int kin, int last) {
    __shared__ __align__(16) unsigned acat[32 * AST];   // tf32 A: cols 0-63 lie, 64-127 lee (16.9 KB)
    __shared__ __align__(16) int2     ebuf[8][32];      // 2 KB edge staging

    const float*    __restrict__ Ein   = g_Ebuf[kin];
    float*          __restrict__ Eout  = g_Ebuf[kin + 1];
    const unsigned* __restrict__ Ehin  = g_Eh[kin & 1];
    unsigned*       __restrict__ Ehout = g_Eh[(kin + 1) & 1];
    const unsigned* __restrict__ wt    = g_wt + kin * 2 * D * D;   // [w1 | w2] tf32

    int tid = threadIdx.x;
    int lane = tid & 31, warp = tid >> 5;
    int rbase = blockIdx.x * 32;

    // ---- phase 1: SpMM. warp handles 4 rows; lane owns feature cols {2*lane, 2*lane+1}
    const float2* __restrict__ E2 = reinterpret_cast<const float2*>(Ein);
    const __half2 hzero = __float2half2_rn(0.f);
#pragma unroll
    for (int rr = 0; rr < 4; rr++) {
        int lrow = warp * 4 + rr;
        int row = rbase + lrow;
        float a0 = 0.f, a1 = 0.f;
        float2 er = make_float2(0.f, 0.f);
        if (row < NTOT) {
            er = E2[(size_t)row * 32 + lane];
            int s = g_rowptr[row], e = g_rowptr[row + 1];
            for (int b0 = s; b0 < e; b0 += 32) {
                int idx = b0 + lane;
                if (idx < e) ebuf[warp][lane] = g_ev[idx];
                __syncwarp();
                int m = e - b0; if (m > 32) m = 32;
                __half2 hacc = hzero;
                int j = 0;
                for (; j + 4 <= m; j += 4) {
                    int2 e0 = ebuf[warp][j + 0];
                    int2 e1 = ebuf[warp][j + 1];
                    int2 e2v = ebuf[warp][j + 2];
                    int2 e3 = ebuf[warp][j + 3];
                    unsigned h0 = Ehin[(size_t)e0.x * 32 + lane];
                    unsigned h1 = Ehin[(size_t)e1.x * 32 + lane];
                    unsigned h2 = Ehin[(size_t)e2v.x * 32 + lane];
                    unsigned h3 = Ehin[(size_t)e3.x * 32 + lane];
                    hacc = __hfma2(*reinterpret_cast<__half2*>(&e0.y),
                                   *reinterpret_cast<__half2*>(&h0), hacc);
                    hacc = __hfma2(*reinterpret_cast<__half2*>(&e1.y),
                                   *reinterpret_cast<__half2*>(&h1), hacc);
                    hacc = __hfma2(*reinterpret_cast<__half2*>(&e2v.y),
                                   *reinterpret_cast<__half2*>(&h2), hacc);
                    hacc = __hfma2(*reinterpret_cast<__half2*>(&e3.y),
                                   *reinterpret_cast<__half2*>(&h3), hacc);
                }
                for (; j < m; j++) {
                    int2 ej = ebuf[warp][j];
                    unsigned hr = Ehin[(size_t)ej.x * 32 + lane];
                    hacc = __hfma2(*reinterpret_cast<__half2*>(&ej.y),
                                   *reinterpret_cast<__half2*>(&hr), hacc);
                }
                float2 fa = __half22float2(hacc);   // flush chunk to fp32
                a0 += fa.x;
                a1 += fa.y;
                __syncwarp();
            }
        }
        // write tf32 A tile: lie at cols 2lane..+1, lee at 64+2lane..+1
        uint2 lie = make_uint2(tf32cvt(a0 + er.x), tf32cvt(a1 + er.y));
        uint2 lee = make_uint2(tf32cvt(a0 * er.x), tf32cvt(a1 * er.y));
        *reinterpret_cast<uint2*>(&acat[lrow * AST + 2 * lane]) = lie;
        *reinterpret_cast<uint2*>(&acat[lrow * AST + 64 + 2 * lane]) = lee;
    }
    __syncthreads();

    // ---- phase 2: tensor-core GEMM; B fragments straight from gmem (L1-hot weights)
    int n0 = warp * 8;
    int fr = lane >> 2, fc = lane & 3;
    float acc[2][4] = {{0.f, 0.f, 0.f, 0.f}, {0.f, 0.f, 0.f, 0.f}};

#pragma unroll
    for (int p = 0; p < 2; p++) {                 // p=0: lie x w1, p=1: lee x w2
        const unsigned* wp = wt + p * D * D;
        int aoff = p * 64;
#pragma unroll
        for (int t = 0; t < 2; t++) {
            int m0 = t * 16;
#pragma unroll
            for (int k0 = 0; k0 < 64; k0 += 8) {
                const unsigned* A = &acat[(m0 + fr) * AST + aoff + k0 + fc];
                unsigned a0 = A[0], a1 = A[8 * AST], a2 = A[4], a3 = A[8 * AST + 4];
                const unsigned* B = &wp[(k0 + fc) * D + n0 + fr];
                unsigned b0 = B[0], b1 = B[4 * D];
                mma_tf32(acc[t], a0, a1, a2, a3, b0, b1);
            }
        }
    }

    // ---- epilogue: bias + leaky + stores (fragment: c0/c1 row fr, c2/c3 row fr+8)
    int cb = n0 + 2 * fc;
    const float* bias_l = g_bias + kin * D;
    float2 bias = make_float2(bias_l[cb], bias_l[cb + 1]);
    float2* EoutV = reinterpret_cast<float2*>(Eout);
    unsigned* EhV = Ehout;
    int colp = (n0 >> 1) + fc;   // float2 column index
#pragma unroll
    for (int t = 0; t < 2; t++) {
#pragma unroll
        for (int h = 0; h < 2; h++) {
            int grow = rbase + t * 16 + fr + h * 8;
            if (grow < NTOT) {
                float vx = acc[t][2 * h] + bias.x;
                float vy = acc[t][2 * h + 1] + bias.y;
                vx = vx >= 0.f ? vx : 0.2f * vx;
                vy = vy >= 0.f ? vy : 0.2f * vy;
                EoutV[(size_t)grow * 32 + colp] = make_float2(vx, vy);
                if (!last) {
                    __half2 hv = __floats2half2_rn(vx, vy);
                    EhV[(size_t)grow * 32 + colp] = *reinterpret_cast<unsigned*>(&hv);
                }
            }
        }
    }
}

// ---------------- final gather + deferred normalization ----------------
__global__ void out_kernel(const int* __restrict__ uidx,
                           const int* __restrict__ pidx,
                           const int* __restrict__ nidx,
                           float* __restrict__ out) {
    int warp = threadIdx.x >> 5, lane = threadIdx.x & 31;
    int g = blockIdx.x * 8 + warp;            // 0..3071
    int b = g & (BATCH - 1);
    int which = g >> 10;
    int row;
    if (which == 0) row = uidx[b];
    else if (which == 1) row = N_USER + pidx[b];
    else row = N_USER + nidx[b];

    float2* dst = reinterpret_cast<float2*>(out) + (size_t)g * 128;
#pragma unroll
    for (int k = 0; k < 4; k++) {
        float2 v = reinterpret_cast<const float2*>(g_Ebuf[k])[(size_t)row * 32 + lane];
        float sc = 1.0f;
        if (k > 0) {
            float ss = v.x * v.x + v.y * v.y;
#pragma unroll
            for (int o = 16; o > 0; o >>= 1) ss += __shfl_xor_sync(0xffffffffu, ss, o);
            sc = 1.0f / fmaxf(sqrtf(ss), 1e-12f);
        }
        dst[k * 32 + lane] = make_float2(v.x * sc, v.y * sc);
    }
}

// ---------------- launch ----------------
extern "C" void kernel_launch(void* const* d_in, const int* in_sizes, int n_in,
                              void* d_out, int out_size) {
    int iUE, iIE, iUF, iL1W, iL1B, iL2W, iL2B, iW1, iB1, iW2, iB2, iLV, iR, iLR, iLC, iUI, iPI, iNI;
    if (n_in >= 18 && in_sizes[2] == 4096) {
        iUE = 0; iIE = 1; iUF = 2; iL1W = 3; iL1B = 4; iL2W = 5; iL2B = 6;
        iW1 = 7; iB1 = 8; iW2 = 9; iB2 = 10; iLV = 11; iR = 12; iLR = 13; iLC = 14;
        iUI = 15; iPI = 16; iNI = 17;
    } else {
        iUE = 0; iIE = 1; iL1W = 2; iL1B = 3; iL2W = 4; iL2B = 5;
        iW1 = 6; iB1 = 7; iW2 = 8; iB2 = 9; iLR = 10; iLC = 11; iLV = 12;
        iUI = 13; iUF = 14; iPI = 15; iNI = 16; iR = 17;
    }

    const float* user_emb = (const float*)d_in[iUE];
    const float* item_emb = (const float*)d_in[iIE];
    const float* user_feat = (const float*)d_in[iUF];
    const float* lin1_w = (const float*)d_in[iL1W];
    const float* lin1_b = (const float*)d_in[iL1B];
    const float* lin2_w = (const float*)d_in[iL2W];
    const float* lin2_b = (const float*)d_in[iL2B];
    const float* w1 = (const float*)d_in[iW1];
    const float* b1 = (const float*)d_in[iB1];
    const float* w2 = (const float*)d_in[iW2];
    const float* b2 = (const float*)d_in[iB2];
    const float* lap_val = (const float*)d_in[iLV];
    const float* ratio = (const float*)d_in[iR];
    const int* lap_row = (const int*)d_in[iLR];
    const int* lap_col = (const int*)d_in[iLC];
    const int* user_idx = (const int*)d_in[iUI];
    const int* pos_idx = (const int*)d_in[iPI];
    const int* neg_idx = (const int*)d_in[iNI];

    // 1: user MLP + winner + histpos + tf32 weight table (one pass)
    fused1_kernel<<<(NNZ + 255) / 256, 256>>>(user_feat, lin1_w, lin1_b, lin2_w, lin2_b,
                                              user_idx, lap_row, w1, b1, w2, b2);
    // 2-3: scan
    blockscan_kernel<<<NBLK, SCANB>>>();
    topscan_kernel<<<1, 256>>>();
    // 4: E0 init (+ finalize rowptr, reset g_cnt)
    initE_kernel<<<(NTOT * 16 + 255) / 256, 256>>>(user_emb, item_emb, ratio);
    // 5: place edges (+ reset g_winner)
    place_kernel<<<(NNZ + 255) / 256, 256>>>(lap_row, lap_col, lap_val);

    // 6-8: 3 fused graph-conv layers
    for (int k = 0; k < NLAY; k++)
        layer_kernel<<<(NTOT + 31) / 32, 256>>>(k, k == NLAY - 1);

    // 9: gather + deferred normalization
    out_kernel<<<3 * BATCH / 8, 256>>>(user_idx, pos_idx, neg_idx, (float*)d_out);
}